// round 8
// baseline (speedup 1.0000x reference)
// Generator_causal on GB300 (compute_103 baseline): warp-level FP8 e4m3 mma.sync +
// ldmatrix. CTA = 512 threads = 4 DECOUPLED 64-row batch tiles (4 warps each,
// per-tile 128-thread named barriers), 64 sequential node-steps. One CTA-wide
// sync per step; Wi + per-step vectors double-buffered and prefetched there.
// Activations/weights scaled x16 into e4m3; f32 accumulation (acc = 256 x true).
#include <cuda_runtime.h>
#include <cuda_bf16.h>
#include <cstdint>

#define NTH    512
#define NTILES 4
#define TILE_R 64

// device scratch: pre-swizzled fp8(16*Wi) tiles + 16*z-column weights
__device__ __align__(16) uint8_t g_wi8[64][16384];
__device__ float g_wic16[64][128];

// ---------------- SMEM map (bytes) ----------------
#define OFF_ACT    1024u      // 4 tiles x 2 bufs x (64x128 fp8 = 8192) = 65536
#define OFF_WIB    66560u     // 2 bufs x 16384 = 32768
#define OFF_WS1    99328u     // 128x128 fp8 swizzled = 16384
#define OFF_WS2    115712u    // 16384
#define OFF_OUT    132096u    // 4 tiles x (64x66 bf16 = 8448) = 33792
#define OFF_VEC    165888u    // mcol[2][64]|wic[2][128]|wfs[2][128]|bis[2][128]|bs1|bs2|part[4][128]
#define SMEM_TOTAL 172544u

// ---------------- helpers ----------------
__device__ __forceinline__ uint32_t smem_u32(const void* p) {
    uint32_t a;
    asm("{ .reg .u64 t; cvta.to.shared.u64 t, %1; cvt.u32.u64 %0, t; }" : "=r"(a) : "l"(p));
    return a;
}
// fp8 tile byte offset: 128B rows, 16B-chunk XOR swizzle. k in BYTES.
__device__ __forceinline__ uint32_t off8b(int m, int k) {
    return (uint32_t)m * 128u + ((uint32_t)k ^ (((uint32_t)m & 7u) * 16u));
}
// same, k in b16 units
__device__ __forceinline__ uint32_t off8u(int m, int u) {
    return (uint32_t)m * 128u + (((uint32_t)u * 2u) ^ (((uint32_t)m & 7u) * 16u));
}
__device__ __forceinline__ uint16_t pk2_e4m3(float lo, float hi) {
    uint16_t r;
    asm("cvt.rn.satfinite.e4m3x2.f32 %0, %1, %2;" : "=h"(r) : "f"(hi), "f"(lo));
    return r;
}
__device__ __forceinline__ uint32_t pk4_e4m3(float v0, float v1, float v2, float v3) {
    uint16_t lo = pk2_e4m3(v0, v1), hi = pk2_e4m3(v2, v3);
    uint32_t r;
    asm("mov.b32 %0, {%1, %2};" : "=r"(r) : "h"(lo), "h"(hi));
    return r;
}
__device__ __forceinline__ uint8_t fp8b(float v) { return (uint8_t)pk2_e4m3(v, 0.f); }
__device__ __forceinline__ void sts32(uint32_t addr, uint32_t v) {
    asm volatile("st.shared.b32 [%0], %1;" :: "r"(addr), "r"(v) : "memory");
}
__device__ __forceinline__ void sts_b16(uint32_t addr, uint16_t v) {
    asm volatile("st.shared.b16 [%0], %1;" :: "r"(addr), "h"(v) : "memory");
}
__device__ __forceinline__ void sts128(uint32_t addr, uint4 v) {
    asm volatile("st.shared.v4.b32 [%0], {%1,%2,%3,%4};"
                 :: "r"(addr), "r"(v.x), "r"(v.y), "r"(v.z), "r"(v.w) : "memory");
}
__device__ __forceinline__ uint32_t lds32(uint32_t addr) {
    uint32_t v;
    asm volatile("ld.shared.b32 %0, [%1];" : "=r"(v) : "r"(addr));
    return v;
}
__device__ __forceinline__ void ldsm4(uint32_t addr, uint32_t* r) {
    asm volatile("ldmatrix.sync.aligned.m8n8.x4.shared.b16 {%0,%1,%2,%3}, [%4];"
                 : "=r"(r[0]), "=r"(r[1]), "=r"(r[2]), "=r"(r[3]) : "r"(addr));
}
__device__ __forceinline__ void mma_fp8(float* c, const uint32_t* a, uint32_t b0, uint32_t b1) {
    asm volatile("mma.sync.aligned.m16n8k32.row.col.f32.e4m3.e4m3.f32 "
                 "{%0,%1,%2,%3}, {%4,%5,%6,%7}, {%8,%9}, {%0,%1,%2,%3};"
                 : "+f"(c[0]), "+f"(c[1]), "+f"(c[2]), "+f"(c[3])
                 : "r"(a[0]), "r"(a[1]), "r"(a[2]), "r"(a[3]), "r"(b0), "r"(b1));
}
#define TILEBAR(t) asm volatile("bar.sync %0, 128;" :: "r"(1 + (t)) : "memory")

// C[32x64] warp tile = A[mrow0..+31, :] @ W[ncol0..+63, :]^T, K = KSTEPS*32 fp8
template<int KSTEPS>
__device__ __forceinline__ void gemm8(uint32_t aBase, uint32_t bBase,
                                      int mrow0, int ncol0, int lane,
                                      float acc[16][4]) {
    #pragma unroll
    for (int t = 0; t < 16; t++) {
        acc[t][0] = 0.f; acc[t][1] = 0.f; acc[t][2] = 0.f; acc[t][3] = 0.f;
    }
    const int lr = lane & 7, lt = (lane >> 3) & 1, lh = lane >> 4;
    #pragma unroll
    for (int ks = 0; ks < KSTEPS; ks++) {
        const int k0 = ks * 16;                       // b16 units
        uint32_t a[2][4];
        #pragma unroll
        for (int mt = 0; mt < 2; mt++)
            ldsm4(aBase + off8u(mrow0 + 16 * mt + lr + lt * 8, k0 + lh * 8), a[mt]);
        #pragma unroll
        for (int nj = 0; nj < 4; nj++) {
            uint32_t b[4];
            ldsm4(bBase + off8u(ncol0 + 16 * nj + lr + lh * 8, k0 + lt * 8), b);
            #pragma unroll
            for (int mt = 0; mt < 2; mt++) {
                mma_fp8(acc[mt * 8 + 2 * nj],     a[mt], b[0], b[1]);
                mma_fp8(acc[mt * 8 + 2 * nj + 1], a[mt], b[2], b[3]);
            }
        }
    }
}

// ---------------- prologue: convert Wi to pre-swizzled fp8(16*w) ----------------
__global__ void prep_wi_kernel(const float* __restrict__ Wi) {
    const int s = blockIdx.x;
    const float* src = Wi + (size_t)s * 8320;
    for (int idx = threadIdx.x; idx < 8320; idx += 256) {
        int n = idx / 65, k = idx - n * 65;
        float v = __ldg(src + idx) * 16.f;
        if (k < 64) g_wi8[s][off8b(n, k)] = fp8b(v);
        else        g_wic16[s][n] = v;
    }
}

// ---------------- main kernel ----------------
__global__ void __launch_bounds__(NTH, 1)
gen_causal_kernel(const float* __restrict__ x,   const float* __restrict__ z,
                  const float* __restrict__ Mg,  const float* __restrict__ bi,
                  const float* __restrict__ Ws1, const float* __restrict__ bs1,
                  const float* __restrict__ Ws2, const float* __restrict__ bs2,
                  const float* __restrict__ wf,  const float* __restrict__ bf,
                  float* __restrict__ out)
{
    extern __shared__ char smem[];
    const int tid  = threadIdx.x;
    const int lane = tid & 31;
    const int w    = tid >> 5;
    const int tile = w >> 2;                    // 0..3
    const int wt2  = w & 3;
    const int tt   = tid & 127;                 // thread within tile
    const int mhalf = wt2 >> 1;
    const int nhalf = wt2 & 1;
    const int mrow0 = mhalf << 5;               // warp's 32 rows (tile-local)
    const int ncol0 = nhalf << 6;               // warp's 64 cols
    const int grp   = lane >> 2, qd = lane & 3;
    const int tbT   = blockIdx.x * (NTILES * TILE_R) + tile * TILE_R;
    const uint32_t sb   = smem_u32(smem);
    const uint32_t actA = sb + OFF_ACT + (uint32_t)tile * 16384u;  // xm / h2
    const uint32_t actB = actA + 8192u;                            // h1
    const uint32_t outT = sb + OFF_OUT + (uint32_t)tile * 8448u;

    float* mcolV = reinterpret_cast<float*>(smem + OFF_VEC);  // [2][64]
    float* wicV  = mcolV + 128;                               // [2][128]
    float* wfsV  = wicV + 256;                                // [2][128]
    float* bisV  = wfsV + 256;                                // [2][128] (16*bi)
    float* bs1s  = bisV + 256;                                // [128] (16*bs1)
    float* bs2s  = bs1s + 128;                                // [128]
    float* partT = bs2s + 128 + tile * 128;                   // [128] per tile

    // ---- one-time init ----
    #pragma unroll 4
    for (int it = 0; it < 8; it++) {            // Ws1/Ws2 -> fp8(16*w), swizzled
        int q = it * NTH + tid;                 // float4 index 0..4095
        int n = q >> 5, k4 = (q & 31) * 4;
        float4 a = __ldg(reinterpret_cast<const float4*>(Ws1) + q);
        float4 b = __ldg(reinterpret_cast<const float4*>(Ws2) + q);
        uint32_t o = off8b(n, k4);
        sts32(sb + OFF_WS1 + o, pk4_e4m3(16.f * a.x, 16.f * a.y, 16.f * a.z, 16.f * a.w));
        sts32(sb + OFF_WS2 + o, pk4_e4m3(16.f * b.x, 16.f * b.y, 16.f * b.z, 16.f * b.w));
    }
    #pragma unroll 4
    for (int it = 0; it < 32; it++) {           // out-state <- x (bf16, stride 66)
        int idx = it * NTH + tid;               // 0..16383
        int tl = idx >> 12;                     // 4096 values per 64-row tile
        int r = (idx >> 6) & 63, c = idx & 63;
        float v = __ldg(x + (size_t)blockIdx.x * 16384 + idx);
        __nv_bfloat16 h = __float2bfloat16_rn(v);
        sts_b16(sb + OFF_OUT + (uint32_t)tl * 8448u + (uint32_t)(r * 66 + c) * 2u,
                *reinterpret_cast<uint16_t*>(&h));
    }
    // Wi buffer 0 (1024 uint4 = 2/thread) + step-0 vectors into slot 0
    #pragma unroll
    for (int it = 0; it < 2; it++) {
        int o = (it * NTH + tid) * 16;
        sts128(sb + OFF_WIB + o, *reinterpret_cast<const uint4*>(g_wi8[0] + o));
    }
    if (tid < 128) {
        wicV[tid] = g_wic16[0][tid];
        wfsV[tid] = __ldg(wf + tid);
        bisV[tid] = 16.f * __ldg(bi + tid);
        bs1s[tid] = 16.f * __ldg(bs1 + tid);
        bs2s[tid] = __ldg(bs2 + tid);
    }
    if (tid < 64) mcolV[tid] = 16.f * __ldg(Mg + tid * 64);
    __syncthreads();

    float acc[16][4];

    #pragma unroll 1
    for (int i = 0; i < 64; i++) {
        const int cur = i & 1, nxt = cur ^ 1;
        // ---- cooperative prefetch of step i+1 (into slot nxt; safe: slot nxt
        //      was last read in step i-1, sealed by the step-boundary sync) ----
        if (i < 63) {
            const uint8_t* srcw = g_wi8[i + 1];
            const uint32_t dst = sb + OFF_WIB + (uint32_t)nxt * 16384u;
            int o0 = tid * 16, o1 = (tid + NTH) * 16;
            sts128(dst + o0, *reinterpret_cast<const uint4*>(srcw + o0));
            sts128(dst + o1, *reinterpret_cast<const uint4*>(srcw + o1));
            if (tid < 128)      wicV[nxt * 128 + tid] = g_wic16[i + 1][tid];
            else if (tid < 256) wfsV[nxt * 128 + tid - 128] = __ldg(wf + (i + 1) * 128 + tid - 128);
            else if (tid < 384) bisV[nxt * 128 + tid - 256] = 16.f * __ldg(bi + (i + 1) * 128 + tid - 256);
            else if (tid < 448) mcolV[nxt * 64 + tid - 384] = 16.f * __ldg(Mg + (tid - 384) * 64 + i + 1);
        }
        const float bfv = __ldg(bf + i);
        float zr[4];
        #pragma unroll
        for (int kq = 0; kq < 4; kq++)
            zr[kq] = __ldg(z + (size_t)(tbT + mrow0 + grp + 8 * kq) * 64 + i);

        // ---- build xm16 = 16 * state * M[:,i] -> actA fp8 (2 threads/row) ----
        {
            const int row = tt >> 1, h = tt & 1;
            const float* mc = mcolV + cur * 64;
            const uint32_t orow = outT + (uint32_t)row * 132u;
            #pragma unroll
            for (int jj = 0; jj < 32; jj += 4) {
                int j = h * 32 + jj;
                uint32_t p0 = lds32(orow + j * 2);
                uint32_t p1 = lds32(orow + j * 2 + 4);
                __nv_bfloat162 b0 = *reinterpret_cast<__nv_bfloat162*>(&p0);
                __nv_bfloat162 b1 = *reinterpret_cast<__nv_bfloat162*>(&p1);
                float v0 = __bfloat162float(b0.x) * mc[j + 0];
                float v1 = __bfloat162float(b0.y) * mc[j + 1];
                float v2 = __bfloat162float(b1.x) * mc[j + 2];
                float v3 = __bfloat162float(b1.y) * mc[j + 3];
                sts32(actA + off8b(row, j), pk4_e4m3(v0, v1, v2, v3));
            }
        }
        TILEBAR(tile);                           // xm ready tile-wide

        // ---- GEMM1: acc = xm @ Wi_i^T (K=64 fp8) ----
        gemm8<2>(actA, sb + OFF_WIB + (uint32_t)cur * 16384u, mrow0, ncol0, lane, acc);

        // ---- epi1: h1_16 = relu(acc/16 + wic16*z + bi16) -> actB ----
        {
            const float* wic = wicV + cur * 128;
            const float* bis = bisV + cur * 128;
            #pragma unroll
            for (int mtl = 0; mtl < 2; mtl++) {
                int rA = mrow0 + 16 * mtl + grp, rB = rA + 8;
                float zA = zr[2 * mtl], zB = zr[2 * mtl + 1];
                #pragma unroll
                for (int nt = 0; nt < 8; nt++) {
                    int c = ncol0 + 8 * nt + 2 * qd;
                    float w0 = wic[c], w1 = wic[c + 1];
                    float b0 = bis[c], b1 = bis[c + 1];
                    float* A = acc[mtl * 8 + nt];
                    float v0 = fmaxf(fmaf(A[0], 0.0625f, fmaf(w0, zA, b0)), 0.f);
                    float v1 = fmaxf(fmaf(A[1], 0.0625f, fmaf(w1, zA, b1)), 0.f);
                    float v2 = fmaxf(fmaf(A[2], 0.0625f, fmaf(w0, zB, b0)), 0.f);
                    float v3 = fmaxf(fmaf(A[3], 0.0625f, fmaf(w1, zB, b1)), 0.f);
                    sts_b16(actB + off8b(rA, c), pk2_e4m3(v0, v1));
                    sts_b16(actB + off8b(rB, c), pk2_e4m3(v2, v3));
                }
            }
        }
        TILEBAR(tile);                           // h1 ready tile-wide

        // ---- GEMM2: acc = h1 @ Ws1^T (K=128 fp8) ----
        gemm8<4>(actB, sb + OFF_WS1, mrow0, ncol0, lane, acc);

        // ---- epi2: h2_16 = relu(acc/16 + bs1_16) -> actA ----
        #pragma unroll
        for (int mtl = 0; mtl < 2; mtl++) {
            int rA = mrow0 + 16 * mtl + grp, rB = rA + 8;
            #pragma unroll
            for (int nt = 0; nt < 8; nt++) {
                int c = ncol0 + 8 * nt + 2 * qd;
                float b0 = bs1s[c], b1 = bs1s[c + 1];
                float* A = acc[mtl * 8 + nt];
                float v0 = fmaxf(fmaf(A[0], 0.0625f, b0), 0.f);
                float v1 = fmaxf(fmaf(A[1], 0.0625f, b1), 0.f);
                float v2 = fmaxf(fmaf(A[2], 0.0625f, b0), 0.f);
                float v3 = fmaxf(fmaf(A[3], 0.0625f, b1), 0.f);
                sts_b16(actA + off8b(rA, c), pk2_e4m3(v0, v1));
                sts_b16(actA + off8b(rB, c), pk2_e4m3(v2, v3));
            }
        }
        TILEBAR(tile);                           // h2 ready tile-wide

        // ---- GEMM3: acc = h2 @ Ws2^T ----
        gemm8<4>(actA, sb + OFF_WS2, mrow0, ncol0, lane, acc);

        // ---- epi3: o = sigmoid( wf . relu(acc/256 + bs2) + bf ) ----
        {
            const float* wfs = wfsV + cur * 128;
            #pragma unroll
            for (int mtl = 0; mtl < 2; mtl++) {
                float pA = 0.f, pB = 0.f;
                #pragma unroll
                for (int nt = 0; nt < 8; nt++) {
                    int c = ncol0 + 8 * nt + 2 * qd;
                    float w0 = wfs[c], w1 = wfs[c + 1];
                    float b0 = bs2s[c], b1 = bs2s[c + 1];
                    float* A = acc[mtl * 8 + nt];
                    pA = fmaf(w0, fmaxf(fmaf(A[0], 0.00390625f, b0), 0.f), pA);
                    pA = fmaf(w1, fmaxf(fmaf(A[1], 0.00390625f, b1), 0.f), pA);
                    pB = fmaf(w0, fmaxf(fmaf(A[2], 0.00390625f, b0), 0.f), pB);
                    pB = fmaf(w1, fmaxf(fmaf(A[3], 0.00390625f, b1), 0.f), pB);
                }
                pA += __shfl_xor_sync(0xffffffffu, pA, 1);
                pA += __shfl_xor_sync(0xffffffffu, pA, 2);
                pB += __shfl_xor_sync(0xffffffffu, pB, 1);
                pB += __shfl_xor_sync(0xffffffffu, pB, 2);
                if (qd == 0) {
                    int rA = mrow0 + 16 * mtl + grp;
                    partT[nhalf * 64 + rA]     = pA;
                    partT[nhalf * 64 + rA + 8] = pB;
                }
            }
        }
        TILEBAR(tile);                           // partials complete
        if (nhalf == 0) {
            int row = mrow0 + lane;              // 32 rows per mhalf warp
            float t = partT[row] + partT[64 + row] + bfv;
            float o = 1.f / (1.f + __expf(-t));
            __nv_bfloat16 h = __float2bfloat16_rn(o);
            sts_b16(outT + (uint32_t)(row * 66 + i) * 2u, *reinterpret_cast<uint16_t*>(&h));
            out[(size_t)(tbT + row) * 64 + i] = o;   // exact f32 final output
        }
        __syncthreads();                         // step boundary (state/bufs sealed)
    }
}

extern "C" void kernel_launch(void* const* d_in, const int* in_sizes, int n_in,
                              void* d_out, int out_size) {
    const float* x   = (const float*)d_in[0];
    const float* z   = (const float*)d_in[1];
    const float* Mg  = (const float*)d_in[2];
    const float* Wi  = (const float*)d_in[3];
    const float* bi  = (const float*)d_in[4];
    const float* Ws1 = (const float*)d_in[5];
    const float* bs1 = (const float*)d_in[6];
    const float* Ws2 = (const float*)d_in[7];
    const float* bs2 = (const float*)d_in[8];
    const float* wf  = (const float*)d_in[9];
    const float* bf  = (const float*)d_in[10];
    float* out = (float*)d_out;

    const int B = in_sizes[0] / 64;              // 65536
    const int grid = B / (NTILES * TILE_R);      // 256

    cudaFuncSetAttribute(gen_causal_kernel,
                         cudaFuncAttributeMaxDynamicSharedMemorySize, SMEM_TOTAL);
    prep_wi_kernel<<<64, 256>>>(Wi);
    gen_causal_kernel<<<grid, NTH, SMEM_TOTAL>>>(x, z, Mg, bi, Ws1, bs1,
                                                 Ws2, bs2, wf, bf, out);
}

// round 9
// speedup vs baseline: 1.0709x; 1.0709x over previous
// Generator_causal on GB300 (compute_103 baseline): warp-level FP8 e4m3 mma.sync +
// ldmatrix. CTA = 256 threads = ONE 128-row batch tile (8 warps), 64 sequential
// node-steps. SMEM trimmed to 112KB so 2 CTAs co-reside per SM (independent
// chains hide latency). Out-state kept in fp8 smem; f32 outputs written exactly.
// Activations/weights scaled x16 into e4m3; f32 accumulation (acc = 256 x true).
#include <cuda_runtime.h>
#include <cuda_bf16.h>
#include <cuda_fp16.h>
#include <cstdint>

#define NTH    256
#define TILE_M 128

__device__ __align__(16) uint8_t g_wi8[64][16384];
__device__ float g_wic16[64][128];

#define OFF_ACT    1024u      // 2 bufs x 16384 = 32768
#define OFF_WIB    33792u     // 2 bufs x 16384 = 32768
#define OFF_WS1    66560u     // 16384
#define OFF_WS2    82944u     // 16384
#define OFF_OUT    99328u     // 128 x 68B fp8 state = 8704
#define OFF_VEC    108032u    // mcol[2][64]|wic[2][128]|wfs|bis|bs1|bs2|part = 4096
#define SMEM_TOTAL 112128u

__device__ __forceinline__ uint32_t smem_u32(const void* p) {
    uint32_t a;
    asm("{ .reg .u64 t; cvta.to.shared.u64 t, %1; cvt.u32.u64 %0, t; }" : "=r"(a) : "l"(p));
    return a;
}
__device__ __forceinline__ uint32_t off8b(int m, int k) {
    return (uint32_t)m * 128u + ((uint32_t)k ^ (((uint32_t)m & 7u) * 16u));
}
__device__ __forceinline__ uint32_t off8u(int m, int u) {
    return (uint32_t)m * 128u + (((uint32_t)u * 2u) ^ (((uint32_t)m & 7u) * 16u));
}
__device__ __forceinline__ uint16_t pk2_e4m3(float lo, float hi) {
    uint16_t r;
    asm("cvt.rn.satfinite.e4m3x2.f32 %0, %1, %2;" : "=h"(r) : "f"(hi), "f"(lo));
    return r;
}
__device__ __forceinline__ uint32_t pk4_e4m3(float v0, float v1, float v2, float v3) {
    uint16_t lo = pk2_e4m3(v0, v1), hi = pk2_e4m3(v2, v3);
    uint32_t r;
    asm("mov.b32 %0, {%1, %2};" : "=r"(r) : "h"(lo), "h"(hi));
    return r;
}
__device__ __forceinline__ uint8_t fp8b(float v) { return (uint8_t)pk2_e4m3(v, 0.f); }
__device__ __forceinline__ void up4_e4m3(uint32_t p, float* f) {
    uint16_t lo = (uint16_t)p, hi = (uint16_t)(p >> 16);
    uint32_t a, b;
    asm("cvt.rn.f16x2.e4m3x2 %0, %1;" : "=r"(a) : "h"(lo));
    asm("cvt.rn.f16x2.e4m3x2 %0, %1;" : "=r"(b) : "h"(hi));
    __half2 ha = *reinterpret_cast<__half2*>(&a);
    __half2 hb = *reinterpret_cast<__half2*>(&b);
    f[0] = __low2float(ha); f[1] = __high2float(ha);
    f[2] = __low2float(hb); f[3] = __high2float(hb);
}
__device__ __forceinline__ void sts32(uint32_t addr, uint32_t v) {
    asm volatile("st.shared.b32 [%0], %1;" :: "r"(addr), "r"(v) : "memory");
}
__device__ __forceinline__ void sts_b16(uint32_t addr, uint16_t v) {
    asm volatile("st.shared.b16 [%0], %1;" :: "r"(addr), "h"(v) : "memory");
}
__device__ __forceinline__ void sts_b8(uint32_t addr, uint32_t v) {
    asm volatile("st.shared.u8 [%0], %1;" :: "r"(addr), "r"(v) : "memory");
}
__device__ __forceinline__ void sts128(uint32_t addr, uint4 v) {
    asm volatile("st.shared.v4.b32 [%0], {%1,%2,%3,%4};"
                 :: "r"(addr), "r"(v.x), "r"(v.y), "r"(v.z), "r"(v.w) : "memory");
}
__device__ __forceinline__ uint32_t lds32(uint32_t addr) {
    uint32_t v;
    asm volatile("ld.shared.b32 %0, [%1];" : "=r"(v) : "r"(addr));
    return v;
}
__device__ __forceinline__ void ldsm4(uint32_t addr, uint32_t* r) {
    asm volatile("ldmatrix.sync.aligned.m8n8.x4.shared.b16 {%0,%1,%2,%3}, [%4];"
                 : "=r"(r[0]), "=r"(r[1]), "=r"(r[2]), "=r"(r[3]) : "r"(addr));
}
__device__ __forceinline__ void mma_fp8(float* c, const uint32_t* a, uint32_t b0, uint32_t b1) {
    asm volatile("mma.sync.aligned.m16n8k32.row.col.f32.e4m3.e4m3.f32 "
                 "{%0,%1,%2,%3}, {%4,%5,%6,%7}, {%8,%9}, {%0,%1,%2,%3};"
                 : "+f"(c[0]), "+f"(c[1]), "+f"(c[2]), "+f"(c[3])
                 : "r"(a[0]), "r"(a[1]), "r"(a[2]), "r"(a[3]), "r"(b0), "r"(b1));
}
#define PAIRBAR(id) asm volatile("bar.sync %0, 64;" :: "r"(id) : "memory")

template<int KSTEPS>
__device__ __forceinline__ void gemm8(uint32_t aBase, uint32_t bBase,
                                      int mrow0, int ncol0, int lane,
                                      float acc[16][4]) {
    #pragma unroll
    for (int t = 0; t < 16; t++) {
        acc[t][0] = 0.f; acc[t][1] = 0.f; acc[t][2] = 0.f; acc[t][3] = 0.f;
    }
    const int lr = lane & 7, lt = (lane >> 3) & 1, lh = lane >> 4;
    #pragma unroll
    for (int ks = 0; ks < KSTEPS; ks++) {
        const int k0 = ks * 16;
        uint32_t a[2][4];
        #pragma unroll
        for (int mt = 0; mt < 2; mt++)
            ldsm4(aBase + off8u(mrow0 + 16 * mt + lr + lt * 8, k0 + lh * 8), a[mt]);
        #pragma unroll
        for (int nj = 0; nj < 4; nj++) {
            uint32_t b[4];
            ldsm4(bBase + off8u(ncol0 + 16 * nj + lr + lh * 8, k0 + lt * 8), b);
            #pragma unroll
            for (int mt = 0; mt < 2; mt++) {
                mma_fp8(acc[mt * 8 + 2 * nj],     a[mt], b[0], b[1]);
                mma_fp8(acc[mt * 8 + 2 * nj + 1], a[mt], b[2], b[3]);
            }
        }
    }
}

__global__ void prep_wi_kernel(const float* __restrict__ Wi) {
    const int s = blockIdx.x;
    const float* src = Wi + (size_t)s * 8320;
    for (int idx = threadIdx.x; idx < 8320; idx += 256) {
        int n = idx / 65, k = idx - n * 65;
        float v = __ldg(src + idx) * 16.f;
        if (k < 64) g_wi8[s][off8b(n, k)] = fp8b(v);
        else        g_wic16[s][n] = v;
    }
}

__global__ void __launch_bounds__(NTH, 2)
gen_causal_kernel(const float* __restrict__ x,   const float* __restrict__ z,
                  const float* __restrict__ Mg,  const float* __restrict__ bi,
                  const float* __restrict__ Ws1, const float* __restrict__ bs1,
                  const float* __restrict__ Ws2, const float* __restrict__ bs2,
                  const float* __restrict__ wf,  const float* __restrict__ bf,
                  float* __restrict__ out)
{
    extern __shared__ char smem[];
    const int tid  = threadIdx.x;
    const int lane = tid & 31;
    const int w    = tid >> 5;
    const int mrow0 = (w >> 1) << 5;
    const int nhalf = w & 1;
    const int ncol0 = nhalf << 6;
    const int pid   = 1 + (w >> 1);
    const int grp   = lane >> 2, qd = lane & 3;
    const int tb    = blockIdx.x * TILE_M;
    const uint32_t sb   = smem_u32(smem);
    const uint32_t actA = sb + OFF_ACT;
    const uint32_t actB = actA + 16384u;
    const uint32_t outT = sb + OFF_OUT;

    float* mcolV = reinterpret_cast<float*>(smem + OFF_VEC);
    float* wicV  = mcolV + 128;
    float* wfsV  = wicV + 256;
    float* bisV  = wfsV + 128;
    float* bs1s  = bisV + 128;
    float* bs2s  = bs1s + 128;
    float* partT = bs2s + 128;

    #pragma unroll 4
    for (int it = 0; it < 16; it++) {
        int q = it * NTH + tid;
        int n = q >> 5, k4 = (q & 31) * 4;
        float4 a = __ldg(reinterpret_cast<const float4*>(Ws1) + q);
        float4 b = __ldg(reinterpret_cast<const float4*>(Ws2) + q);
        uint32_t o = off8b(n, k4);
        sts32(sb + OFF_WS1 + o, pk4_e4m3(16.f * a.x, 16.f * a.y, 16.f * a.z, 16.f * a.w));
        sts32(sb + OFF_WS2 + o, pk4_e4m3(16.f * b.x, 16.f * b.y, 16.f * b.z, 16.f * b.w));
    }
    #pragma unroll 4
    for (int it = 0; it < 8; it++) {
        int q = it * NTH + tid;
        int r = q >> 4, c4 = (q & 15) << 2;
        float4 v = __ldg(reinterpret_cast<const float4*>(x) + (size_t)blockIdx.x * 2048 + q);
        sts32(outT + (uint32_t)(r * 68 + c4), pk4_e4m3(v.x, v.y, v.z, v.w));
    }
    #pragma unroll
    for (int it = 0; it < 4; it++) {
        int o = (it * NTH + tid) * 16;
        sts128(sb + OFF_WIB + o, *reinterpret_cast<const uint4*>(g_wi8[0] + o));
    }
    if (tid < 128) {
        wicV[tid] = g_wic16[0][tid];
        bs1s[tid] = 16.f * __ldg(bs1 + tid);
        bs2s[tid] = __ldg(bs2 + tid);
    }
    if (tid < 64) mcolV[tid] = 16.f * __ldg(Mg + tid * 64);
    __syncthreads();

    float acc[16][4];

    #pragma unroll 1
    for (int i = 0; i < 64; i++) {
        const int cur = i & 1, nxt = cur ^ 1;
        if (tid < 128) {
            wfsV[tid] = __ldg(wf + i * 128 + tid);
            bisV[tid] = 16.f * __ldg(bi + i * 128 + tid);
        } else if (tid < 192 && i < 63) {
            mcolV[nxt * 64 + tid - 128] = 16.f * __ldg(Mg + (tid - 128) * 64 + i + 1);
        }
        const float bfv = __ldg(bf + i);
        float zr[4];
        #pragma unroll
        for (int kq = 0; kq < 4; kq++)
            zr[kq] = __ldg(z + (size_t)(tb + mrow0 + grp + 8 * kq) * 64 + i);

        // ---- xm16 = (16*M[:,i]) * state -> actA fp8 (2 threads/row) ----
        {
            const int row = tid >> 1, h = tid & 1;
            const float* mc = mcolV + cur * 64;
            const uint32_t orow = outT + (uint32_t)row * 68u;
            #pragma unroll
            for (int jj = 0; jj < 32; jj += 4) {
                int j = h * 32 + jj;
                float s[4];
                up4_e4m3(lds32(orow + j), s);
                sts32(actA + off8b(row, j),
                      pk4_e4m3(s[0] * mc[j + 0], s[1] * mc[j + 1],
                               s[2] * mc[j + 2], s[3] * mc[j + 3]));
            }
        }
        __syncthreads();                        // xm + vectors visible

        // ---- GEMM1 ----
        gemm8<2>(actA, sb + OFF_WIB + (uint32_t)cur * 16384u, mrow0, ncol0, lane, acc);
        if (i < 63) {                           // prefetch next Wi
            const uint8_t* srcw = g_wi8[i + 1];
            const uint32_t dst = sb + OFF_WIB + (uint32_t)nxt * 16384u;
            #pragma unroll
            for (int it = 0; it < 4; it++) {
                int o = (it * NTH + tid) * 16;
                sts128(dst + o, *reinterpret_cast<const uint4*>(srcw + o));
            }
            if (tid < 128) wicV[nxt * 128 + tid] = g_wic16[i + 1][tid];
        }

        // ---- epi1 -> actB ----
        {
            const float* wic = wicV + cur * 128;
            #pragma unroll
            for (int mtl = 0; mtl < 2; mtl++) {
                int rA = mrow0 + 16 * mtl + grp, rB = rA + 8;
                float zA = zr[2 * mtl], zB = zr[2 * mtl + 1];
                #pragma unroll
                for (int nt = 0; nt < 8; nt++) {
                    int c = ncol0 + 8 * nt + 2 * qd;
                    float w0 = wic[c], w1 = wic[c + 1];
                    float b0 = bisV[c], b1 = bisV[c + 1];
                    float* A = acc[mtl * 8 + nt];
                    float v0 = fmaxf(fmaf(A[0], 0.0625f, fmaf(w0, zA, b0)), 0.f);
                    float v1 = fmaxf(fmaf(A[1], 0.0625f, fmaf(w1, zA, b1)), 0.f);
                    float v2 = fmaxf(fmaf(A[2], 0.0625f, fmaf(w0, zB, b0)), 0.f);
                    float v3 = fmaxf(fmaf(A[3], 0.0625f, fmaf(w1, zB, b1)), 0.f);
                    sts_b16(actB + off8b(rA, c), pk2_e4m3(v0, v1));
                    sts_b16(actB + off8b(rB, c), pk2_e4m3(v2, v3));
                }
            }
        }
        __syncthreads();                        // h1 complete

        // ---- GEMM2 ----
        gemm8<4>(actB, sb + OFF_WS1, mrow0, ncol0, lane, acc);

        // ---- epi2 -> actA ----
        #pragma unroll
        for (int mtl = 0; mtl < 2; mtl++) {
            int rA = mrow0 + 16 * mtl + grp, rB = rA + 8;
            #pragma unroll
            for (int nt = 0; nt < 8; nt++) {
                int c = ncol0 + 8 * nt + 2 * qd;
                float b0 = bs1s[c], b1 = bs1s[c + 1];
                float* A = acc[mtl * 8 + nt];
                sts_b16(actA + off8b(rA, c),
                        pk2_e4m3(fmaxf(fmaf(A[0], 0.0625f, b0), 0.f),
                                 fmaxf(fmaf(A[1], 0.0625f, b1), 0.f)));
                sts_b16(actA + off8b(rB, c),
                        pk2_e4m3(fmaxf(fmaf(A[2], 0.0625f, b0), 0.f),
                                 fmaxf(fmaf(A[3], 0.0625f, b1), 0.f)));
            }
        }
        __syncthreads();                        // h2 complete

        // ---- GEMM3 ----
        gemm8<4>(actA, sb + OFF_WS2, mrow0, ncol0, lane, acc);

        // ---- epi3: o = sigmoid( wf . relu(acc/256 + bs2) + bf ) ----
        float pA0 = 0.f, pB0 = 0.f, pA1 = 0.f, pB1 = 0.f;
        #pragma unroll
        for (int nt = 0; nt < 8; nt++) {
            int c = ncol0 + 8 * nt + 2 * qd;
            float w0 = wfsV[c], w1 = wfsV[c + 1];
            float b0 = bs2s[c], b1 = bs2s[c + 1];
            float* A0 = acc[nt];
            float* A1 = acc[8 + nt];
            pA0 = fmaf(w0, fmaxf(fmaf(A0[0], 0.00390625f, b0), 0.f), pA0);
            pA0 = fmaf(w1, fmaxf(fmaf(A0[1], 0.00390625f, b1), 0.f), pA0);
            pB0 = fmaf(w0, fmaxf(fmaf(A0[2], 0.00390625f, b0), 0.f), pB0);
            pB0 = fmaf(w1, fmaxf(fmaf(A0[3], 0.00390625f, b1), 0.f), pB0);
            pA1 = fmaf(w0, fmaxf(fmaf(A1[0], 0.00390625f, b0), 0.f), pA1);
            pA1 = fmaf(w1, fmaxf(fmaf(A1[1], 0.00390625f, b1), 0.f), pA1);
            pB1 = fmaf(w0, fmaxf(fmaf(A1[2], 0.00390625f, b0), 0.f), pB1);
            pB1 = fmaf(w1, fmaxf(fmaf(A1[3], 0.00390625f, b1), 0.f), pB1);
        }
        pA0 += __shfl_xor_sync(0xffffffffu, pA0, 1);
        pA0 += __shfl_xor_sync(0xffffffffu, pA0, 2);
        pB0 += __shfl_xor_sync(0xffffffffu, pB0, 1);
        pB0 += __shfl_xor_sync(0xffffffffu, pB0, 2);
        pA1 += __shfl_xor_sync(0xffffffffu, pA1, 1);
        pA1 += __shfl_xor_sync(0xffffffffu, pA1, 2);
        pB1 += __shfl_xor_sync(0xffffffffu, pB1, 1);
        pB1 += __shfl_xor_sync(0xffffffffu, pB1, 2);
        if (qd == 0 && nhalf == 1) {           // publish col-half-1 partials
            partT[mrow0 + grp]      = pA0;
            partT[mrow0 + grp + 8]  = pB0;
            partT[mrow0 + grp + 16] = pA1;
            partT[mrow0 + grp + 24] = pB1;
        }
        PAIRBAR(pid);
        if (qd == 0 && nhalf == 0) {           // combine + sigmoid + store
            int r0 = mrow0 + grp;
            float t0 = pA0 + partT[r0]      + bfv;
            float t1 = pB0 + partT[r0 + 8]  + bfv;
            float t2 = pA1 + partT[r0 + 16] + bfv;
            float t3 = pB1 + partT[r0 + 24] + bfv;
            float o0 = 1.f / (1.f + __expf(-t0));
            float o1 = 1.f / (1.f + __expf(-t1));
            float o2 = 1.f / (1.f + __expf(-t2));
            float o3 = 1.f / (1.f + __expf(-t3));
            sts_b8(outT + (uint32_t)((r0)      * 68 + i), (uint32_t)fp8b(o0));
            sts_b8(outT + (uint32_t)((r0 + 8)  * 68 + i), (uint32_t)fp8b(o1));
            sts_b8(outT + (uint32_t)((r0 + 16) * 68 + i), (uint32_t)fp8b(o2));
            sts_b8(outT + (uint32_t)((r0 + 24) * 68 + i), (uint32_t)fp8b(o3));
            out[(size_t)(tb + r0)      * 64 + i] = o0;   // exact f32 output
            out[(size_t)(tb + r0 + 8)  * 64 + i] = o1;
            out[(size_t)(tb + r0 + 16) * 64 + i] = o2;
            out[(size_t)(tb + r0 + 24) * 64 + i] = o3;
        }
        __syncthreads();                        // step boundary
    }
}

extern "C" void kernel_launch(void* const* d_in, const int* in_sizes, int n_in,
                              void* d_out, int out_size) {
    const float* x   = (const float*)d_in[0];
    const float* z   = (const float*)d_in[1];
    const float* Mg  = (const float*)d_in[2];
    const float* Wi  = (const float*)d_in[3];
    const float* bi  = (const float*)d_in[4];
    const float* Ws1 = (const float*)d_in[5];
    const float* bs1 = (const float*)d_in[6];
    const float* Ws2 = (const float*)d_in[7];
    const float* bs2 = (const float*)d_in[8];
    const float* wf  = (const float*)d_in[9];
    const float* bf  = (const float*)d_in[10];
    float* out = (float*)d_out;

    const int B = in_sizes[0] / 64;              // 65536
    const int grid = B / TILE_M;                 // 512

    cudaFuncSetAttribute(gen_causal_kernel,
                         cudaFuncAttributeMaxDynamicSharedMemorySize, SMEM_TOTAL);
    prep_wi_kernel<<<64, 256>>>(Wi);
    gen_causal_kernel<<<grid, NTH, SMEM_TOTAL>>>(x, z, Mg, bi, Ws1, bs1,
                                                 Ws2, bs2, wf, bf, out);
}

// round 10
// speedup vs baseline: 1.0854x; 1.0136x over previous
// Generator_causal on GB300 (compute_103 baseline): warp-level FP8 e4m3 mma.sync +
// ldmatrix. CTA = 256 threads = ONE 128-row batch tile (8 warps = 4 warp pairs),
// 64 sequential node-steps. ALL intra-step sync is pair-local (bar.sync id,64):
// each pair owns its 32 rows end-to-end; weights are read-only shared. One CTA
// __syncthreads per step seals the double-buffered Wi/vector prefetch. 2 CTAs/SM.
// Activations/weights scaled x16 into e4m3; f32 accumulation (acc = 256 x true).
#include <cuda_runtime.h>
#include <cuda_bf16.h>
#include <cuda_fp16.h>
#include <cstdint>

#define NTH    256
#define TILE_M 128

__device__ __align__(16) uint8_t g_wi8[64][16384];
__device__ float g_wic16[64][128];

#define OFF_ACT    1024u      // 2 bufs x 16384 = 32768
#define OFF_WIB    33792u     // 2 bufs x 16384 = 32768
#define OFF_WS1    66560u     // 16384
#define OFF_WS2    82944u     // 16384
#define OFF_OUT    99328u     // 128 x 68B fp8 state = 8704
#define OFF_VEC    108032u    // mcol[2][64]|wic[2][128]|wfs[2][128]|bis[2][128]|bs1|bs2|part = 5120
#define SMEM_TOTAL 113152u

__device__ __forceinline__ uint32_t smem_u32(const void* p) {
    uint32_t a;
    asm("{ .reg .u64 t; cvta.to.shared.u64 t, %1; cvt.u32.u64 %0, t; }" : "=r"(a) : "l"(p));
    return a;
}
__device__ __forceinline__ uint32_t off8b(int m, int k) {
    return (uint32_t)m * 128u + ((uint32_t)k ^ (((uint32_t)m & 7u) * 16u));
}
__device__ __forceinline__ uint16_t pk2_e4m3(float lo, float hi) {
    uint16_t r;
    asm("cvt.rn.satfinite.e4m3x2.f32 %0, %1, %2;" : "=h"(r) : "f"(hi), "f"(lo));
    return r;
}
__device__ __forceinline__ uint32_t pk4_e4m3(float v0, float v1, float v2, float v3) {
    uint16_t lo = pk2_e4m3(v0, v1), hi = pk2_e4m3(v2, v3);
    uint32_t r;
    asm("mov.b32 %0, {%1, %2};" : "=r"(r) : "h"(lo), "h"(hi));
    return r;
}
__device__ __forceinline__ uint8_t fp8b(float v) { return (uint8_t)pk2_e4m3(v, 0.f); }
__device__ __forceinline__ void up4_e4m3(uint32_t p, float* f) {
    uint16_t lo = (uint16_t)p, hi = (uint16_t)(p >> 16);
    uint32_t a, b;
    asm("cvt.rn.f16x2.e4m3x2 %0, %1;" : "=r"(a) : "h"(lo));
    asm("cvt.rn.f16x2.e4m3x2 %0, %1;" : "=r"(b) : "h"(hi));
    __half2 ha = *reinterpret_cast<__half2*>(&a);
    __half2 hb = *reinterpret_cast<__half2*>(&b);
    f[0] = __low2float(ha); f[1] = __high2float(ha);
    f[2] = __low2float(hb); f[3] = __high2float(hb);
}
__device__ __forceinline__ void sts32(uint32_t addr, uint32_t v) {
    asm volatile("st.shared.b32 [%0], %1;" :: "r"(addr), "r"(v) : "memory");
}
__device__ __forceinline__ void sts_b16(uint32_t addr, uint16_t v) {
    asm volatile("st.shared.b16 [%0], %1;" :: "r"(addr), "h"(v) : "memory");
}
__device__ __forceinline__ void sts_b8(uint32_t addr, uint32_t v) {
    asm volatile("st.shared.u8 [%0], %1;" :: "r"(addr), "r"(v) : "memory");
}
__device__ __forceinline__ void sts128(uint32_t addr, uint4 v) {
    asm volatile("st.shared.v4.b32 [%0], {%1,%2,%3,%4};"
                 :: "r"(addr), "r"(v.x), "r"(v.y), "r"(v.z), "r"(v.w) : "memory");
}
__device__ __forceinline__ uint32_t lds32(uint32_t addr) {
    uint32_t v;
    asm volatile("ld.shared.b32 %0, [%1];" : "=r"(v) : "r"(addr));
    return v;
}
__device__ __forceinline__ void ldsm4(uint32_t addr, uint32_t* r) {
    asm volatile("ldmatrix.sync.aligned.m8n8.x4.shared.b16 {%0,%1,%2,%3}, [%4];"
                 : "=r"(r[0]), "=r"(r[1]), "=r"(r[2]), "=r"(r[3]) : "r"(addr));
}
__device__ __forceinline__ void mma_fp8(float* c, const uint32_t* a, uint32_t b0, uint32_t b1) {
    asm volatile("mma.sync.aligned.m16n8k32.row.col.f32.e4m3.e4m3.f32 "
                 "{%0,%1,%2,%3}, {%4,%5,%6,%7}, {%8,%9}, {%0,%1,%2,%3};"
                 : "+f"(c[0]), "+f"(c[1]), "+f"(c[2]), "+f"(c[3])
                 : "r"(a[0]), "r"(a[1]), "r"(a[2]), "r"(a[3]), "r"(b0), "r"(b1));
}
#define PAIRBAR(id) asm volatile("bar.sync %0, 64;" :: "r"(id) : "memory")

// C[32x64] warp tile; ldsm row bases + swizzle XOR hoisted out of the k-loop.
template<int KSTEPS>
__device__ __forceinline__ void gemm8(uint32_t aBase, uint32_t bBase,
                                      int mrow0, int ncol0, int lane,
                                      float acc[16][4]) {
    #pragma unroll
    for (int t = 0; t < 16; t++) {
        acc[t][0] = 0.f; acc[t][1] = 0.f; acc[t][2] = 0.f; acc[t][3] = 0.f;
    }
    const int lr = lane & 7, lt = (lane >> 3) & 1, lh = lane >> 4;
    uint32_t aRow[2], aXor[2], bRow[4], bXor[4];
    #pragma unroll
    for (int mt = 0; mt < 2; mt++) {
        int m = mrow0 + 16 * mt + lr + lt * 8;
        aRow[mt] = aBase + (uint32_t)m * 128u;
        aXor[mt] = ((uint32_t)m & 7u) * 16u;
    }
    #pragma unroll
    for (int nj = 0; nj < 4; nj++) {
        int n = ncol0 + 16 * nj + lr + lh * 8;
        bRow[nj] = bBase + (uint32_t)n * 128u;
        bXor[nj] = ((uint32_t)n & 7u) * 16u;
    }
    #pragma unroll
    for (int ks = 0; ks < KSTEPS; ks++) {
        const uint32_t ka = (uint32_t)(ks * 32 + lh * 16);   // byte k-offset (A)
        const uint32_t kb = (uint32_t)(ks * 32 + lt * 16);   // byte k-offset (B)
        uint32_t a[2][4];
        #pragma unroll
        for (int mt = 0; mt < 2; mt++)
            ldsm4(aRow[mt] + (ka ^ aXor[mt]), a[mt]);
        #pragma unroll
        for (int nj = 0; nj < 4; nj++) {
            uint32_t b[4];
            ldsm4(bRow[nj] + (kb ^ bXor[nj]), b);
            #pragma unroll
            for (int mt = 0; mt < 2; mt++) {
                mma_fp8(acc[mt * 8 + 2 * nj],     a[mt], b[0], b[1]);
                mma_fp8(acc[mt * 8 + 2 * nj + 1], a[mt], b[2], b[3]);
            }
        }
    }
}

__global__ void prep_wi_kernel(const float* __restrict__ Wi) {
    const int s = blockIdx.x;
    const float* src = Wi + (size_t)s * 8320;
    for (int idx = threadIdx.x; idx < 8320; idx += 256) {
        int n = idx / 65, k = idx - n * 65;
        float v = __ldg(src + idx) * 16.f;
        if (k < 64) g_wi8[s][off8b(n, k)] = fp8b(v);
        else        g_wic16[s][n] = v;
    }
}

__global__ void __launch_bounds__(NTH, 2)
gen_causal_kernel(const float* __restrict__ x,   const float* __restrict__ z,
                  const float* __restrict__ Mg,  const float* __restrict__ bi,
                  const float* __restrict__ Ws1, const float* __restrict__ bs1,
                  const float* __restrict__ Ws2, const float* __restrict__ bs2,
                  const float* __restrict__ wf,  const float* __restrict__ bf,
                  float* __restrict__ out)
{
    extern __shared__ char smem[];
    const int tid  = threadIdx.x;
    const int lane = tid & 31;
    const int w    = tid >> 5;
    const int pair = w >> 1;                    // 0..3
    const int tp   = tid & 63;                  // thread within pair
    const int mrow0 = pair << 5;                // pair's 32 rows
    const int nhalf = w & 1;
    const int ncol0 = nhalf << 6;               // warp's 64 cols
    const int pid   = 1 + pair;                 // named barrier id (1..4)
    const int grp   = lane >> 2, qd = lane & 3;
    const int tb    = blockIdx.x * TILE_M;
    const uint32_t sb   = smem_u32(smem);
    const uint32_t actA = sb + OFF_ACT;         // xm / h2
    const uint32_t actB = actA + 16384u;        // h1
    const uint32_t outT = sb + OFF_OUT;         // fp8 state, 68B stride

    float* mcolV = reinterpret_cast<float*>(smem + OFF_VEC);  // [2][64]
    float* wicV  = mcolV + 128;                               // [2][128]
    float* wfsV  = wicV + 256;                                // [2][128]
    float* bisV  = wfsV + 256;                                // [2][128] (16*bi)
    float* bs1s  = bisV + 256;                                // [128] (16*bs1)
    float* bs2s  = bs1s + 128;                                // [128]
    float* partT = bs2s + 128;                                // [128] (rows disjoint per pair)

    // ---- one-time init ----
    #pragma unroll 4
    for (int it = 0; it < 16; it++) {           // Ws1/Ws2 -> fp8(16*w), swizzled
        int q = it * NTH + tid;                 // float4 index 0..4095
        int n = q >> 5, k4 = (q & 31) * 4;
        float4 a = __ldg(reinterpret_cast<const float4*>(Ws1) + q);
        float4 b = __ldg(reinterpret_cast<const float4*>(Ws2) + q);
        uint32_t o = off8b(n, k4);
        sts32(sb + OFF_WS1 + o, pk4_e4m3(16.f * a.x, 16.f * a.y, 16.f * a.z, 16.f * a.w));
        sts32(sb + OFF_WS2 + o, pk4_e4m3(16.f * b.x, 16.f * b.y, 16.f * b.z, 16.f * b.w));
    }
    #pragma unroll 4
    for (int it = 0; it < 8; it++) {            // state <- fp8(x), 68B stride
        int q = it * NTH + tid;                 // word index 0..2047
        int r = q >> 4, c4 = (q & 15) << 2;
        float4 v = __ldg(reinterpret_cast<const float4*>(x) + (size_t)blockIdx.x * 2048 + q);
        sts32(outT + (uint32_t)(r * 68 + c4), pk4_e4m3(v.x, v.y, v.z, v.w));
    }
    #pragma unroll
    for (int it = 0; it < 4; it++) {            // Wi buffer 0
        int o = (it * NTH + tid) * 16;
        sts128(sb + OFF_WIB + o, *reinterpret_cast<const uint4*>(g_wi8[0] + o));
    }
    if (tid < 128) {
        wicV[tid] = g_wic16[0][tid];
        wfsV[tid] = __ldg(wf + tid);
        bisV[tid] = 16.f * __ldg(bi + tid);
        bs1s[tid] = 16.f * __ldg(bs1 + tid);
        bs2s[tid] = __ldg(bs2 + tid);
    }
    if (tid < 64) mcolV[tid] = 16.f * __ldg(Mg + tid * 64);
    __syncthreads();

    float acc[16][4];

    #pragma unroll 1
    for (int i = 0; i < 64; i++) {
        const int cur = i & 1, nxt = cur ^ 1;
        const float bfv = __ldg(bf + i);
        float zr[4];
        #pragma unroll
        for (int kq = 0; kq < 4; kq++)
            zr[kq] = __ldg(z + (size_t)(tb + mrow0 + grp + 8 * kq) * 64 + i);

        // ---- xm16 = (16*M[:,i]) * state -> actA, PAIR-LOCAL rows ----
        {
            const int row = mrow0 + (tp >> 1), h = tp & 1;
            const float* mc = mcolV + cur * 64;
            const uint32_t orow = outT + (uint32_t)row * 68u;
            #pragma unroll
            for (int jj = 0; jj < 32; jj += 4) {
                int j = h * 32 + jj;
                float s[4];
                up4_e4m3(lds32(orow + j), s);
                sts32(actA + off8b(row, j),
                      pk4_e4m3(s[0] * mc[j + 0], s[1] * mc[j + 1],
                               s[2] * mc[j + 2], s[3] * mc[j + 3]));
            }
        }
        PAIRBAR(pid);                           // pair's xm rows ready

        // ---- GEMM1: acc = xm @ Wi_i^T (K=64 fp8) ----
        gemm8<2>(actA, sb + OFF_WIB + (uint32_t)cur * 16384u, mrow0, ncol0, lane, acc);

        // ---- cooperative prefetch of step i+1 (sealed by boundary sync) ----
        if (i < 63) {
            const uint8_t* srcw = g_wi8[i + 1];
            const uint32_t dst = sb + OFF_WIB + (uint32_t)nxt * 16384u;
            #pragma unroll
            for (int it = 0; it < 4; it++) {
                int o = (it * NTH + tid) * 16;
                sts128(dst + o, *reinterpret_cast<const uint4*>(srcw + o));
            }
            if (tid < 128) {
                wicV[nxt * 128 + tid] = g_wic16[i + 1][tid];
                wfsV[nxt * 128 + tid] = __ldg(wf + (i + 1) * 128 + tid);
            } else {
                bisV[nxt * 128 + tid - 128] = 16.f * __ldg(bi + (i + 1) * 128 + tid - 128);
                if (tid < 192)
                    mcolV[nxt * 64 + tid - 128] = 16.f * __ldg(Mg + (tid - 128) * 64 + i + 1);
            }
        }

        // ---- epi1: h1_16 = relu(acc/16 + wic16*z + bi16) -> actB (pair rows) ----
        {
            const float* wic = wicV + cur * 128;
            const float* bis = bisV + cur * 128;
            #pragma unroll
            for (int mtl = 0; mtl < 2; mtl++) {
                int rA = mrow0 + 16 * mtl + grp, rB = rA + 8;
                float zA = zr[2 * mtl], zB = zr[2 * mtl + 1];
                #pragma unroll
                for (int nt = 0; nt < 8; nt++) {
                    int c = ncol0 + 8 * nt + 2 * qd;
                    float w0 = wic[c], w1 = wic[c + 1];
                    float b0 = bis[c], b1 = bis[c + 1];
                    float* A = acc[mtl * 8 + nt];
                    float v0 = fmaxf(fmaf(A[0], 0.0625f, fmaf(w0, zA, b0)), 0.f);
                    float v1 = fmaxf(fmaf(A[1], 0.0625f, fmaf(w1, zA, b1)), 0.f);
                    float v2 = fmaxf(fmaf(A[2], 0.0625f, fmaf(w0, zB, b0)), 0.f);
                    float v3 = fmaxf(fmaf(A[3], 0.0625f, fmaf(w1, zB, b1)), 0.f);
                    sts_b16(actB + off8b(rA, c), pk2_e4m3(v0, v1));
                    sts_b16(actB + off8b(rB, c), pk2_e4m3(v2, v3));
                }
            }
        }
        PAIRBAR(pid);                           // pair's h1 rows complete

        // ---- GEMM2: acc = h1 @ Ws1^T (K=128 fp8) ----
        gemm8<4>(actB, sb + OFF_WS1, mrow0, ncol0, lane, acc);

        // ---- epi2: h2_16 = relu(acc/16 + bs1_16) -> actA (pair rows) ----
        #pragma unroll
        for (int mtl = 0; mtl < 2; mtl++) {
            int rA = mrow0 + 16 * mtl + grp, rB = rA + 8;
            #pragma unroll
            for (int nt = 0; nt < 8; nt++) {
                int c = ncol0 + 8 * nt + 2 * qd;
                float b0 = bs1s[c], b1 = bs1s[c + 1];
                float* A = acc[mtl * 8 + nt];
                sts_b16(actA + off8b(rA, c),
                        pk2_e4m3(fmaxf(fmaf(A[0], 0.0625f, b0), 0.f),
                                 fmaxf(fmaf(A[1], 0.0625f, b1), 0.f)));
                sts_b16(actA + off8b(rB, c),
                        pk2_e4m3(fmaxf(fmaf(A[2], 0.0625f, b0), 0.f),
                                 fmaxf(fmaf(A[3], 0.0625f, b1), 0.f)));
            }
        }
        PAIRBAR(pid);                           // pair's h2 rows complete

        // ---- GEMM3: acc = h2 @ Ws2^T ----
        gemm8<4>(actA, sb + OFF_WS2, mrow0, ncol0, lane, acc);

        // ---- epi3: o = sigmoid( wf . relu(acc/256 + bs2) + bf ) ----
        {
            const float* wfs = wfsV + cur * 128;
            float pA0 = 0.f, pB0 = 0.f, pA1 = 0.f, pB1 = 0.f;
            #pragma unroll
            for (int nt = 0; nt < 8; nt++) {
                int c = ncol0 + 8 * nt + 2 * qd;
                float w0 = wfs[c], w1 = wfs[c + 1];
                float b0 = bs2s[c], b1 = bs2s[c + 1];
                float* A0 = acc[nt];
                float* A1 = acc[8 + nt];
                pA0 = fmaf(w0, fmaxf(fmaf(A0[0], 0.00390625f, b0), 0.f), pA0);
                pA0 = fmaf(w1, fmaxf(fmaf(A0[1], 0.00390625f, b1), 0.f), pA0);
                pB0 = fmaf(w0, fmaxf(fmaf(A0[2], 0.00390625f, b0), 0.f), pB0);
                pB0 = fmaf(w1, fmaxf(fmaf(A0[3], 0.00390625f, b1), 0.f), pB0);
                pA1 = fmaf(w0, fmaxf(fmaf(A1[0], 0.00390625f, b0), 0.f), pA1);
                pA1 = fmaf(w1, fmaxf(fmaf(A1[1], 0.00390625f, b1), 0.f), pA1);
                pB1 = fmaf(w0, fmaxf(fmaf(A1[2], 0.00390625f, b0), 0.f), pB1);
                pB1 = fmaf(w1, fmaxf(fmaf(A1[3], 0.00390625f, b1), 0.f), pB1);
            }
            pA0 += __shfl_xor_sync(0xffffffffu, pA0, 1);
            pA0 += __shfl_xor_sync(0xffffffffu, pA0, 2);
            pB0 += __shfl_xor_sync(0xffffffffu, pB0, 1);
            pB0 += __shfl_xor_sync(0xffffffffu, pB0, 2);
            pA1 += __shfl_xor_sync(0xffffffffu, pA1, 1);
            pA1 += __shfl_xor_sync(0xffffffffu, pA1, 2);
            pB1 += __shfl_xor_sync(0xffffffffu, pB1, 1);
            pB1 += __shfl_xor_sync(0xffffffffu, pB1, 2);
            if (qd == 0 && nhalf == 1) {        // publish col-half-1 partials
                partT[mrow0 + grp]      = pA0;
                partT[mrow0 + grp + 8]  = pB0;
                partT[mrow0 + grp + 16] = pA1;
                partT[mrow0 + grp + 24] = pB1;
            }
            PAIRBAR(pid);
            if (qd == 0 && nhalf == 0) {        // combine + sigmoid + store
                int r0 = mrow0 + grp;
                float t0 = pA0 + partT[r0]      + bfv;
                float t1 = pB0 + partT[r0 + 8]  + bfv;
                float t2 = pA1 + partT[r0 + 16] + bfv;
                float t3 = pB1 + partT[r0 + 24] + bfv;
                float o0 = 1.f / (1.f + __expf(-t0));
                float o1 = 1.f / (1.f + __expf(-t1));
                float o2 = 1.f / (1.f + __expf(-t2));
                float o3 = 1.f / (1.f + __expf(-t3));
                sts_b8(outT + (uint32_t)((r0)      * 68 + i), (uint32_t)fp8b(o0));
                sts_b8(outT + (uint32_t)((r0 + 8)  * 68 + i), (uint32_t)fp8b(o1));
                sts_b8(outT + (uint32_t)((r0 + 16) * 68 + i), (uint32_t)fp8b(o2));
                sts_b8(outT + (uint32_t)((r0 + 24) * 68 + i), (uint32_t)fp8b(o3));
                out[(size_t)(tb + r0)      * 64 + i] = o0;   // exact f32 output
                out[(size_t)(tb + r0 + 8)  * 64 + i] = o1;
                out[(size_t)(tb + r0 + 16) * 64 + i] = o2;
                out[(size_t)(tb + r0 + 24) * 64 + i] = o3;
            }
        }
        __syncthreads();                        // step boundary: Wi/vec bufs sealed
    }
}

extern "C" void kernel_launch(void* const* d_in, const int* in_sizes, int n_in,
                              void* d_out, int out_size) {
    const float* x   = (const float*)d_in[0];
    const float* z   = (const float*)d_in[1];
    const float* Mg  = (const float*)d_in[2];
    const float* Wi  = (const float*)d_in[3];
    const float* bi  = (const float*)d_in[4];
    const float* Ws1 = (const float*)d_in[5];
    const float* bs1 = (const float*)d_in[6];
    const float* Ws2 = (const float*)d_in[7];
    const float* bs2 = (const float*)d_in[8];
    const float* wf  = (const float*)d_in[9];
    const float* bf  = (const float*)d_in[10];
    float* out = (float*)d_out;

    const int B = in_sizes[0] / 64;              // 65536
    const int grid = B / TILE_M;                 // 512

    cudaFuncSetAttribute(gen_causal_kernel,
                         cudaFuncAttributeMaxDynamicSharedMemorySize, SMEM_TOTAL);
    prep_wi_kernel<<<64, 256>>>(Wi);
    gen_causal_kernel<<<grid, NTH, SMEM_TOTAL>>>(x, z, Mg, bi, Ws1, bs1,
                                                 Ws2, bs2, wf, bf, out);
}

// round 11
// speedup vs baseline: 1.1036x; 1.0167x over previous
// Generator_causal on GB300 (compute_103 baseline): warp-level FP8 e4m3 mma.sync +
// ldmatrix. CTA = 256 threads = ONE 128-row batch tile (8 warps = 4 warp pairs).
// Adjacency mask folded into Wi offline: GEMM1 reads the persistent fp8 state
// tile directly (no per-step xm phase). C-zero first-kstep mma kills acc-zeroing.
// Pair-local barriers for all intra-step deps; one CTA sync per step seals the
// double-buffered Wi/vector prefetch. 2 CTAs/SM.
// Scales: state=fp8(v); WiM=fp8(128*Wi*M); Ws=fp8(16*Ws); h=fp8(16*h).
#include <cuda_runtime.h>
#include <cuda_bf16.h>
#include <cstdint>

#define NTH    256
#define TILE_M 128

// device scratch: pre-swizzled fp8(128*Wi*Mcol) tiles + 16*z-column weights
__device__ __align__(16) uint8_t g_wi8[64][16384];
__device__ float g_wic16[64][128];

#define OFF_STATE  1024u      // 128x128B fp8 swizzled state tile (cols 0..63 used)
#define OFF_ACTH   17408u     // 16384: h1 and h2 (shared, alternating)
#define OFF_WIB    33792u     // 2 bufs x 16384
#define OFF_WS1    66560u     // 16384
#define OFF_WS2    82944u     // 16384
#define OFF_VEC    99328u     // wic[2][128]|wfs[2][128]|bis[2][128]|bs1|bs2|part = 4608
#define SMEM_TOTAL 103936u

__device__ __forceinline__ uint32_t smem_u32(const void* p) {
    uint32_t a;
    asm("{ .reg .u64 t; cvta.to.shared.u64 t, %1; cvt.u32.u64 %0, t; }" : "=r"(a) : "l"(p));
    return a;
}
__device__ __forceinline__ uint32_t off8b(int m, int k) {
    return (uint32_t)m * 128u + ((uint32_t)k ^ (((uint32_t)m & 7u) * 16u));
}
__device__ __forceinline__ uint16_t pk2_e4m3(float lo, float hi) {
    uint16_t r;
    asm("cvt.rn.satfinite.e4m3x2.f32 %0, %1, %2;" : "=h"(r) : "f"(hi), "f"(lo));
    return r;
}
__device__ __forceinline__ uint32_t pk4_e4m3(float v0, float v1, float v2, float v3) {
    uint16_t lo = pk2_e4m3(v0, v1), hi = pk2_e4m3(v2, v3);
    uint32_t r;
    asm("mov.b32 %0, {%1, %2};" : "=r"(r) : "h"(lo), "h"(hi));
    return r;
}
__device__ __forceinline__ uint8_t fp8b(float v) { return (uint8_t)pk2_e4m3(v, 0.f); }
__device__ __forceinline__ void sts32(uint32_t addr, uint32_t v) {
    asm volatile("st.shared.b32 [%0], %1;" :: "r"(addr), "r"(v) : "memory");
}
__device__ __forceinline__ void sts_b16(uint32_t addr, uint16_t v) {
    asm volatile("st.shared.b16 [%0], %1;" :: "r"(addr), "h"(v) : "memory");
}
__device__ __forceinline__ void sts_b8(uint32_t addr, uint32_t v) {
    asm volatile("st.shared.u8 [%0], %1;" :: "r"(addr), "r"(v) : "memory");
}
__device__ __forceinline__ void sts128(uint32_t addr, uint4 v) {
    asm volatile("st.shared.v4.b32 [%0], {%1,%2,%3,%4};"
                 :: "r"(addr), "r"(v.x), "r"(v.y), "r"(v.z), "r"(v.w) : "memory");
}
__device__ __forceinline__ void ldsm4(uint32_t addr, uint32_t* r) {
    asm volatile("ldmatrix.sync.aligned.m8n8.x4.shared.b16 {%0,%1,%2,%3}, [%4];"
                 : "=r"(r[0]), "=r"(r[1]), "=r"(r[2]), "=r"(r[3]) : "r"(addr));
}
__device__ __forceinline__ void mma_fp8(float* c, const uint32_t* a, uint32_t b0, uint32_t b1) {
    asm volatile("mma.sync.aligned.m16n8k32.row.col.f32.e4m3.e4m3.f32 "
                 "{%0,%1,%2,%3}, {%4,%5,%6,%7}, {%8,%9}, {%0,%1,%2,%3};"
                 : "+f"(c[0]), "+f"(c[1]), "+f"(c[2]), "+f"(c[3])
                 : "r"(a[0]), "r"(a[1]), "r"(a[2]), "r"(a[3]), "r"(b0), "r"(b1));
}
// first-kstep form: D = A*B + 0 (no acc-zero MOVs needed)
__device__ __forceinline__ void mma_fp8_z(float* d, const uint32_t* a, uint32_t b0, uint32_t b1) {
    asm volatile("mma.sync.aligned.m16n8k32.row.col.f32.e4m3.e4m3.f32 "
                 "{%0,%1,%2,%3}, {%4,%5,%6,%7}, {%8,%9}, {%10,%11,%12,%13};"
                 : "=f"(d[0]), "=f"(d[1]), "=f"(d[2]), "=f"(d[3])
                 : "r"(a[0]), "r"(a[1]), "r"(a[2]), "r"(a[3]), "r"(b0), "r"(b1),
                   "f"(0.f), "f"(0.f), "f"(0.f), "f"(0.f));
}
#define PAIRBAR(id) asm volatile("bar.sync %0, 64;" :: "r"(id) : "memory")

// C[32x64] warp tile; ldsm bases hoisted; kstep 0 uses C=0 mma form.
template<int KSTEPS>
__device__ __forceinline__ void gemm8(uint32_t aBase, uint32_t bBase,
                                      int mrow0, int ncol0, int lane,
                                      float acc[16][4]) {
    const int lr = lane & 7, lt = (lane >> 3) & 1, lh = lane >> 4;
    uint32_t aRow[2], aXor[2], bRow[4], bXor[4];
    #pragma unroll
    for (int mt = 0; mt < 2; mt++) {
        int m = mrow0 + 16 * mt + lr + lt * 8;
        aRow[mt] = aBase + (uint32_t)m * 128u;
        aXor[mt] = ((uint32_t)m & 7u) * 16u;
    }
    #pragma unroll
    for (int nj = 0; nj < 4; nj++) {
        int n = ncol0 + 16 * nj + lr + lh * 8;
        bRow[nj] = bBase + (uint32_t)n * 128u;
        bXor[nj] = ((uint32_t)n & 7u) * 16u;
    }
    #pragma unroll
    for (int ks = 0; ks < KSTEPS; ks++) {
        const uint32_t ka = (uint32_t)(ks * 32 + lh * 16);
        const uint32_t kb = (uint32_t)(ks * 32 + lt * 16);
        uint32_t a[2][4];
        #pragma unroll
        for (int mt = 0; mt < 2; mt++)
            ldsm4(aRow[mt] + (ka ^ aXor[mt]), a[mt]);
        #pragma unroll
        for (int nj = 0; nj < 4; nj++) {
            uint32_t b[4];
            ldsm4(bRow[nj] + (kb ^ bXor[nj]), b);
            #pragma unroll
            for (int mt = 0; mt < 2; mt++) {
                if (ks == 0) {
                    mma_fp8_z(acc[mt * 8 + 2 * nj],     a[mt], b[0], b[1]);
                    mma_fp8_z(acc[mt * 8 + 2 * nj + 1], a[mt], b[2], b[3]);
                } else {
                    mma_fp8(acc[mt * 8 + 2 * nj],     a[mt], b[0], b[1]);
                    mma_fp8(acc[mt * 8 + 2 * nj + 1], a[mt], b[2], b[3]);
                }
            }
        }
    }
}

// prologue: fold adjacency column into Wi -> fp8(128 * Wi * M[k][s]); z-col x16
__global__ void prep_wi_kernel(const float* __restrict__ Wi, const float* __restrict__ Mg) {
    const int s = blockIdx.x;
    const float* src = Wi + (size_t)s * 8320;
    for (int idx = threadIdx.x; idx < 8320; idx += 256) {
        int n = idx / 65, k = idx - n * 65;
        float v = __ldg(src + idx);
        if (k < 64) g_wi8[s][off8b(n, k)] = fp8b(128.f * v * __ldg(Mg + k * 64 + s));
        else        g_wic16[s][n] = 16.f * v;
    }
}

__global__ void __launch_bounds__(NTH, 2)
gen_causal_kernel(const float* __restrict__ x,   const float* __restrict__ z,
                  const float* __restrict__ bi,  const float* __restrict__ Ws1,
                  const float* __restrict__ bs1, const float* __restrict__ Ws2,
                  const float* __restrict__ bs2, const float* __restrict__ wf,
                  const float* __restrict__ bf,  float* __restrict__ out)
{
    extern __shared__ char smem[];
    const int tid  = threadIdx.x;
    const int lane = tid & 31;
    const int w    = tid >> 5;
    const int pair = w >> 1;                    // 0..3
    const int mrow0 = pair << 5;                // pair's 32 rows
    const int nhalf = w & 1;
    const int ncol0 = nhalf << 6;               // warp's 64 cols
    const int pid   = 1 + pair;                 // named barrier id
    const int grp   = lane >> 2, qd = lane & 3;
    const int tb    = blockIdx.x * TILE_M;
    const uint32_t sb     = smem_u32(smem);
    const uint32_t stateT = sb + OFF_STATE;
    const uint32_t actH   = sb + OFF_ACTH;

    float* wicV = reinterpret_cast<float*>(smem + OFF_VEC);   // [2][128]
    float* wfsV = wicV + 256;                                 // [2][128]
    float* bisV = wfsV + 256;                                 // [2][128] (16*bi)
    float* bs1s = bisV + 256;                                 // [128] (16*bs1)
    float* bs2s = bs1s + 128;                                 // [128]
    float* partT = bs2s + 128;                                // [128]
    const float2* wic2a = reinterpret_cast<const float2*>(wicV);
    const float2* wfs2a = reinterpret_cast<const float2*>(wfsV);
    const float2* bis2a = reinterpret_cast<const float2*>(bisV);
    const float2* bs12  = reinterpret_cast<const float2*>(bs1s);
    const float2* bs22  = reinterpret_cast<const float2*>(bs2s);

    // ---- one-time init ----
    #pragma unroll 4
    for (int it = 0; it < 16; it++) {           // Ws1/Ws2 -> fp8(16*w), swizzled
        int q = it * NTH + tid;
        int n = q >> 5, k4 = (q & 31) * 4;
        float4 a = __ldg(reinterpret_cast<const float4*>(Ws1) + q);
        float4 b = __ldg(reinterpret_cast<const float4*>(Ws2) + q);
        uint32_t o = off8b(n, k4);
        sts32(sb + OFF_WS1 + o, pk4_e4m3(16.f * a.x, 16.f * a.y, 16.f * a.z, 16.f * a.w));
        sts32(sb + OFF_WS2 + o, pk4_e4m3(16.f * b.x, 16.f * b.y, 16.f * b.z, 16.f * b.w));
    }
    #pragma unroll 4
    for (int it = 0; it < 8; it++) {            // state <- fp8(x), swizzled tile
        int q = it * NTH + tid;                 // word index 0..2047
        int r = q >> 4, c4 = (q & 15) << 2;
        float4 v = __ldg(reinterpret_cast<const float4*>(x) + (size_t)blockIdx.x * 2048 + q);
        sts32(stateT + off8b(r, c4), pk4_e4m3(v.x, v.y, v.z, v.w));
    }
    #pragma unroll
    for (int it = 0; it < 4; it++) {            // Wi buffer 0
        int o = (it * NTH + tid) * 16;
        sts128(sb + OFF_WIB + o, *reinterpret_cast<const uint4*>(g_wi8[0] + o));
    }
    if (tid < 128) {
        wicV[tid] = g_wic16[0][tid];
        wfsV[tid] = __ldg(wf + tid);
        bisV[tid] = 16.f * __ldg(bi + tid);
        bs1s[tid] = 16.f * __ldg(bs1 + tid);
        bs2s[tid] = __ldg(bs2 + tid);
    }
    __syncthreads();

    float acc[16][4];
    const float* zbase = z + (size_t)(tb + mrow0 + grp) * 64;

    #pragma unroll 1
    for (int i = 0; i < 64; i++) {
        const int cur = i & 1, nxt = cur ^ 1;
        const float bfv = __ldg(bf + i);
        float zr[4];
        #pragma unroll
        for (int kq = 0; kq < 4; kq++)
            zr[kq] = __ldg(zbase + kq * 512 + i);

        // ---- GEMM1: acc = state @ (Wi∘M)^T  (K=64 fp8, A = persistent state) ----
        gemm8<2>(stateT, sb + OFF_WIB + (uint32_t)cur * 16384u, mrow0, ncol0, lane, acc);

        // ---- cooperative prefetch of step i+1 (sealed by boundary sync) ----
        if (i < 63) {
            const uint8_t* srcw = g_wi8[i + 1];
            const uint32_t dst = sb + OFF_WIB + (uint32_t)nxt * 16384u;
            #pragma unroll
            for (int it = 0; it < 4; it++) {
                int o = (it * NTH + tid) * 16;
                sts128(dst + o, *reinterpret_cast<const uint4*>(srcw + o));
            }
            if (tid < 128) {
                wicV[nxt * 128 + tid] = g_wic16[i + 1][tid];
                wfsV[nxt * 128 + tid] = __ldg(wf + (i + 1) * 128 + tid);
            } else {
                bisV[nxt * 128 + tid - 128] = 16.f * __ldg(bi + (i + 1) * 128 + tid - 128);
            }
        }

        // ---- epi1: h1_16 = relu(acc/8 + wic16*z + bi16) -> actH ----
        // (acc = 128 x true; h stored at 16 x true -> factor 0.125)
        {
            const float2* wic2 = wic2a + cur * 64;
            const float2* bis2 = bis2a + cur * 64;
            #pragma unroll
            for (int mtl = 0; mtl < 2; mtl++) {
                int rA = mrow0 + 16 * mtl + grp, rB = rA + 8;
                float zA = zr[2 * mtl], zB = zr[2 * mtl + 1];
                #pragma unroll
                for (int nt = 0; nt < 8; nt++) {
                    int c = ncol0 + 8 * nt + 2 * qd;
                    float2 wv = wic2[c >> 1];
                    float2 bv = bis2[c >> 1];
                    float* A = acc[mtl * 8 + nt];
                    float v0 = fmaxf(fmaf(A[0], 0.125f, fmaf(wv.x, zA, bv.x)), 0.f);
                    float v1 = fmaxf(fmaf(A[1], 0.125f, fmaf(wv.y, zA, bv.y)), 0.f);
                    float v2 = fmaxf(fmaf(A[2], 0.125f, fmaf(wv.x, zB, bv.x)), 0.f);
                    float v3 = fmaxf(fmaf(A[3], 0.125f, fmaf(wv.y, zB, bv.y)), 0.f);
                    sts_b16(actH + off8b(rA, c), pk2_e4m3(v0, v1));
                    sts_b16(actH + off8b(rB, c), pk2_e4m3(v2, v3));
                }
            }
        }
        PAIRBAR(pid);                           // pair's h1 rows complete

        // ---- GEMM2: acc = h1 @ Ws1^T (K=128 fp8) ----
        gemm8<4>(actH, sb + OFF_WS1, mrow0, ncol0, lane, acc);
        PAIRBAR(pid);                           // pair done reading h1 rows

        // ---- epi2: h2_16 = relu(acc/16 + bs1_16) -> actH (reuse) ----
        #pragma unroll
        for (int mtl = 0; mtl < 2; mtl++) {
            int rA = mrow0 + 16 * mtl + grp, rB = rA + 8;
            #pragma unroll
            for (int nt = 0; nt < 8; nt++) {
                int c = ncol0 + 8 * nt + 2 * qd;
                float2 bv = bs12[c >> 1];
                float* A = acc[mtl * 8 + nt];
                sts_b16(actH + off8b(rA, c),
                        pk2_e4m3(fmaxf(fmaf(A[0], 0.0625f, bv.x), 0.f),
                                 fmaxf(fmaf(A[1], 0.0625f, bv.y), 0.f)));
                sts_b16(actH + off8b(rB, c),
                        pk2_e4m3(fmaxf(fmaf(A[2], 0.0625f, bv.x), 0.f),
                                 fmaxf(fmaf(A[3], 0.0625f, bv.y), 0.f)));
            }
        }
        PAIRBAR(pid);                           // pair's h2 rows complete

        // ---- GEMM3: acc = h2 @ Ws2^T ----
        gemm8<4>(actH, sb + OFF_WS2, mrow0, ncol0, lane, acc);

        // ---- epi3: o = sigmoid( wf . relu(acc/256 + bs2) + bf ) ----
        {
            const float2* wfs2 = wfs2a + cur * 64;
            float pA0 = 0.f, pB0 = 0.f, pA1 = 0.f, pB1 = 0.f;
            #pragma unroll
            for (int nt = 0; nt < 8; nt++) {
                int c = ncol0 + 8 * nt + 2 * qd;
                float2 wv = wfs2[c >> 1];
                float2 bv = bs22[c >> 1];
                float* A0 = acc[nt];
                float* A1 = acc[8 + nt];
                pA0 = fmaf(wv.x, fmaxf(fmaf(A0[0], 0.00390625f, bv.x), 0.f), pA0);
                pA0 = fmaf(wv.y, fmaxf(fmaf(A0[1], 0.00390625f, bv.y), 0.f), pA0);
                pB0 = fmaf(wv.x, fmaxf(fmaf(A0[2], 0.00390625f, bv.x), 0.f), pB0);
                pB0 = fmaf(wv.y, fmaxf(fmaf(A0[3], 0.00390625f, bv.y), 0.f), pB0);
                pA1 = fmaf(wv.x, fmaxf(fmaf(A1[0], 0.00390625f, bv.x), 0.f), pA1);
                pA1 = fmaf(wv.y, fmaxf(fmaf(A1[1], 0.00390625f, bv.y), 0.f), pA1);
                pB1 = fmaf(wv.x, fmaxf(fmaf(A1[2], 0.00390625f, bv.x), 0.f), pB1);
                pB1 = fmaf(wv.y, fmaxf(fmaf(A1[3], 0.00390625f, bv.y), 0.f), pB1);
            }
            pA0 += __shfl_xor_sync(0xffffffffu, pA0, 1);
            pA0 += __shfl_xor_sync(0xffffffffu, pA0, 2);
            pB0 += __shfl_xor_sync(0xffffffffu, pB0, 1);
            pB0 += __shfl_xor_sync(0xffffffffu, pB0, 2);
            pA1 += __shfl_xor_sync(0xffffffffu, pA1, 1);
            pA1 += __shfl_xor_sync(0xffffffffu, pA1, 2);
            pB1 += __shfl_xor_sync(0xffffffffu, pB1, 1);
            pB1 += __shfl_xor_sync(0xffffffffu, pB1, 2);
            if (qd == 0 && nhalf == 1) {        // publish col-half-1 partials
                partT[mrow0 + grp]      = pA0;
                partT[mrow0 + grp + 8]  = pB0;
                partT[mrow0 + grp + 16] = pA1;
                partT[mrow0 + grp + 24] = pB1;
            }
            PAIRBAR(pid);
            if (qd == 0 && nhalf == 0) {        // combine + sigmoid + store
                int r0 = mrow0 + grp;
                float t0 = pA0 + partT[r0]      + bfv;
                float t1 = pB0 + partT[r0 + 8]  + bfv;
                float t2 = pA1 + partT[r0 + 16] + bfv;
                float t3 = pB1 + partT[r0 + 24] + bfv;
                float o0 = 1.f / (1.f + __expf(-t0));
                float o1 = 1.f / (1.f + __expf(-t1));
                float o2 = 1.f / (1.f + __expf(-t2));
                float o3 = 1.f / (1.f + __expf(-t3));
                sts_b8(stateT + off8b(r0,      i), (uint32_t)fp8b(o0));
                sts_b8(stateT + off8b(r0 + 8,  i), (uint32_t)fp8b(o1));
                sts_b8(stateT + off8b(r0 + 16, i), (uint32_t)fp8b(o2));
                sts_b8(stateT + off8b(r0 + 24, i), (uint32_t)fp8b(o3));
                out[(size_t)(tb + r0)      * 64 + i] = o0;   // exact f32 output
                out[(size_t)(tb + r0 + 8)  * 64 + i] = o1;
                out[(size_t)(tb + r0 + 16) * 64 + i] = o2;
                out[(size_t)(tb + r0 + 24) * 64 + i] = o3;
            }
        }
        __syncthreads();                        // step boundary: state + bufs sealed
    }
}

extern "C" void kernel_launch(void* const* d_in, const int* in_sizes, int n_in,
                              void* d_out, int out_size) {
    const float* x   = (const float*)d_in[0];
    const float* z   = (const float*)d_in[1];
    const float* Mg  = (const float*)d_in[2];
    const float* Wi  = (const float*)d_in[3];
    const float* bi  = (const float*)d_in[4];
    const float* Ws1 = (const float*)d_in[5];
    const float* bs1 = (const float*)d_in[6];
    const float* Ws2 = (const float*)d_in[7];
    const float* bs2 = (const float*)d_in[8];
    const float* wf  = (const float*)d_in[9];
    const float* bf  = (const float*)d_in[10];
    float* out = (float*)d_out;

    const int B = in_sizes[0] / 64;              // 65536
    const int grid = B / TILE_M;                 // 512

    cudaFuncSetAttribute(gen_causal_kernel,
                         cudaFuncAttributeMaxDynamicSharedMemorySize, SMEM_TOTAL);
    prep_wi_kernel<<<64, 256>>>(Wi, Mg);
    gen_causal_kernel<<<grid, NTH, SMEM_TOTAL>>>(x, z, bi, Ws1, bs1,
                                                 Ws2, bs2, wf, bf, out);
}

// round 12
// speedup vs baseline: 1.1569x; 1.0483x over previous
// Generator_causal on GB300 (compute_103 baseline): warp-level FP8 e4m3 mma.sync +
// ldmatrix. CTA = 256 threads = ONE 128-row batch tile (8 warps = 4 warp pairs).
// NO swizzle: padded-stride smem layouts (144B rows for K=128 tiles, 80B rows for
// K=64 tiles) are ldmatrix-conflict-free with purely LINEAR addressing -> large
// integer-instruction reduction. Separate h1/h2 buffers (one fewer barrier).
// Adjacency mask folded into Wi offline; C-zero first-kstep mma; pair-local
// barriers; one CTA sync per step seals the Wi/vector prefetch. 2 CTAs/SM.
// Scales: state=fp8(v); WiM=fp8(128*Wi*M); Ws=fp8(16*Ws); h=fp8(16*h).
#include <cuda_runtime.h>
#include <cuda_bf16.h>
#include <cstdint>

#define NTH    256
#define TILE_M 128

// device scratch: pre-packed fp8(128*Wi*Mcol) tiles (80B row stride) + z-col wts
__device__ __align__(16) uint8_t g_wi8[64][10240];
__device__ float g_wic16[64][128];

// ---------------- SMEM map (bytes); all tile bases 1024-aligned ----------------
#define OFF_STATE  1024u      // 128 rows x 80B (cols 0..63 used) = 10240
#define OFF_ACT1   11264u     // h1: 128 rows x 144B = 18432
#define OFF_ACT2   29696u     // h2: 128 rows x 144B = 18432
#define OFF_WIB    48128u     // 2 bufs x (128 x 80B) = 20480
#define OFF_WS1    68608u     // 128 x 144B = 18432
#define OFF_WS2    87040u     // 18432
#define OFF_VEC    105472u    // wic[2][128]|wfs[2][128]|bis[2][128]|bs1|bs2|part = 4608
#define SMEM_TOTAL 110080u

// ---------------- helpers ----------------
__device__ __forceinline__ uint32_t smem_u32(const void* p) {
    uint32_t a;
    asm("{ .reg .u64 t; cvta.to.shared.u64 t, %1; cvt.u32.u64 %0, t; }" : "=r"(a) : "l"(p));
    return a;
}
__device__ __forceinline__ uint16_t pk2_e4m3(float lo, float hi) {
    uint16_t r;
    asm("cvt.rn.satfinite.e4m3x2.f32 %0, %1, %2;" : "=h"(r) : "f"(hi), "f"(lo));
    return r;
}
__device__ __forceinline__ uint32_t pk4_e4m3(float v0, float v1, float v2, float v3) {
    uint16_t lo = pk2_e4m3(v0, v1), hi = pk2_e4m3(v2, v3);
    uint32_t r;
    asm("mov.b32 %0, {%1, %2};" : "=r"(r) : "h"(lo), "h"(hi));
    return r;
}
__device__ __forceinline__ uint8_t fp8b(float v) { return (uint8_t)pk2_e4m3(v, 0.f); }
__device__ __forceinline__ void sts32(uint32_t addr, uint32_t v) {
    asm volatile("st.shared.b32 [%0], %1;" :: "r"(addr), "r"(v) : "memory");
}
__device__ __forceinline__ void sts_b16(uint32_t addr, uint16_t v) {
    asm volatile("st.shared.b16 [%0], %1;" :: "r"(addr), "h"(v) : "memory");
}
__device__ __forceinline__ void sts_b8(uint32_t addr, uint32_t v) {
    asm volatile("st.shared.u8 [%0], %1;" :: "r"(addr), "r"(v) : "memory");
}
__device__ __forceinline__ void sts128(uint32_t addr, uint4 v) {
    asm volatile("st.shared.v4.b32 [%0], {%1,%2,%3,%4};"
                 :: "r"(addr), "r"(v.x), "r"(v.y), "r"(v.z), "r"(v.w) : "memory");
}
__device__ __forceinline__ void ldsm4(uint32_t addr, uint32_t* r) {
    asm volatile("ldmatrix.sync.aligned.m8n8.x4.shared.b16 {%0,%1,%2,%3}, [%4];"
                 : "=r"(r[0]), "=r"(r[1]), "=r"(r[2]), "=r"(r[3]) : "r"(addr));
}
__device__ __forceinline__ void mma_fp8(float* c, const uint32_t* a, uint32_t b0, uint32_t b1) {
    asm volatile("mma.sync.aligned.m16n8k32.row.col.f32.e4m3.e4m3.f32 "
                 "{%0,%1,%2,%3}, {%4,%5,%6,%7}, {%8,%9}, {%0,%1,%2,%3};"
                 : "+f"(c[0]), "+f"(c[1]), "+f"(c[2]), "+f"(c[3])
                 : "r"(a[0]), "r"(a[1]), "r"(a[2]), "r"(a[3]), "r"(b0), "r"(b1));
}
// first-kstep form: D = A*B + 0 (no acc-zero MOVs)
__device__ __forceinline__ void mma_fp8_z(float* d, const uint32_t* a, uint32_t b0, uint32_t b1) {
    asm volatile("mma.sync.aligned.m16n8k32.row.col.f32.e4m3.e4m3.f32 "
                 "{%0,%1,%2,%3}, {%4,%5,%6,%7}, {%8,%9}, {%10,%11,%12,%13};"
                 : "=f"(d[0]), "=f"(d[1]), "=f"(d[2]), "=f"(d[3])
                 : "r"(a[0]), "r"(a[1]), "r"(a[2]), "r"(a[3]), "r"(b0), "r"(b1),
                   "f"(0.f), "f"(0.f), "f"(0.f), "f"(0.f));
}
#define PAIRBAR(id) asm volatile("bar.sync %0, 64;" :: "r"(id) : "memory")

// C[32x64] warp tile = A[mrow0..+31, :] @ W[ncol0..+63, :]^T.
// AST/BST = row strides in bytes (80 or 144); purely linear addressing.
template<int KSTEPS, int AST, int BST>
__device__ __forceinline__ void gemm8(uint32_t aBase, uint32_t bBase,
                                      int mrow0, int ncol0, int lane,
                                      float acc[16][4]) {
    const int lr = lane & 7, lt = (lane >> 3) & 1, lh = lane >> 4;
    uint32_t aRow[2], bRow[4];
    #pragma unroll
    for (int mt = 0; mt < 2; mt++)
        aRow[mt] = aBase + (uint32_t)(mrow0 + 16 * mt + lr + lt * 8) * AST
                 + (uint32_t)(lh * 16);
    #pragma unroll
    for (int nj = 0; nj < 4; nj++)
        bRow[nj] = bBase + (uint32_t)(ncol0 + 16 * nj + lr + lh * 8) * BST
                 + (uint32_t)(lt * 16);
    #pragma unroll
    for (int ks = 0; ks < KSTEPS; ks++) {
        const uint32_t kk = (uint32_t)(ks * 32);
        uint32_t a[2][4];
        #pragma unroll
        for (int mt = 0; mt < 2; mt++)
            ldsm4(aRow[mt] + kk, a[mt]);
        #pragma unroll
        for (int nj = 0; nj < 4; nj++) {
            uint32_t b[4];
            ldsm4(bRow[nj] + kk, b);
            #pragma unroll
            for (int mt = 0; mt < 2; mt++) {
                if (ks == 0) {
                    mma_fp8_z(acc[mt * 8 + 2 * nj],     a[mt], b[0], b[1]);
                    mma_fp8_z(acc[mt * 8 + 2 * nj + 1], a[mt], b[2], b[3]);
                } else {
                    mma_fp8(acc[mt * 8 + 2 * nj],     a[mt], b[0], b[1]);
                    mma_fp8(acc[mt * 8 + 2 * nj + 1], a[mt], b[2], b[3]);
                }
            }
        }
    }
}

// prologue: fold adjacency column into Wi -> fp8(128 * Wi * M[k][s]), 80B rows
__global__ void prep_wi_kernel(const float* __restrict__ Wi, const float* __restrict__ Mg) {
    const int s = blockIdx.x;
    const float* src = Wi + (size_t)s * 8320;
    for (int idx = threadIdx.x; idx < 8320; idx += 256) {
        int n = idx / 65, k = idx - n * 65;
        float v = __ldg(src + idx);
        if (k < 64) g_wi8[s][n * 80 + k] = fp8b(128.f * v * __ldg(Mg + k * 64 + s));
        else        g_wic16[s][n] = 16.f * v;
    }
}

__global__ void __launch_bounds__(NTH, 2)
gen_causal_kernel(const float* __restrict__ x,   const float* __restrict__ z,
                  const float* __restrict__ bi,  const float* __restrict__ Ws1,
                  const float* __restrict__ bs1, const float* __restrict__ Ws2,
                  const float* __restrict__ bs2, const float* __restrict__ wf,
                  const float* __restrict__ bf,  float* __restrict__ out)
{
    extern __shared__ char smem[];
    const int tid  = threadIdx.x;
    const int lane = tid & 31;
    const int w    = tid >> 5;
    const int pair = w >> 1;                    // 0..3
    const int mrow0 = pair << 5;                // pair's 32 rows
    const int nhalf = w & 1;
    const int ncol0 = nhalf << 6;               // warp's 64 cols
    const int pid   = 1 + pair;                 // named barrier id
    const int grp   = lane >> 2, qd = lane & 3;
    const int tb    = blockIdx.x * TILE_M;
    const uint32_t sb     = smem_u32(smem);
    const uint32_t stateT = sb + OFF_STATE;     // 80B rows
    const uint32_t act1   = sb + OFF_ACT1;      // 144B rows
    const uint32_t act2   = sb + OFF_ACT2;      // 144B rows

    float* wicV = reinterpret_cast<float*>(smem + OFF_VEC);   // [2][128]
    float* wfsV = wicV + 256;                                 // [2][128]
    float* bisV = wfsV + 256;                                 // [2][128] (16*bi)
    float* bs1s = bisV + 256;                                 // [128] (16*bs1)
    float* bs2s = bs1s + 128;                                 // [128]
    float* partT = bs2s + 128;                                // [128]
    const float2* wic2a = reinterpret_cast<const float2*>(wicV);
    const float2* wfs2a = reinterpret_cast<const float2*>(wfsV);
    const float2* bis2a = reinterpret_cast<const float2*>(bisV);
    const float2* bs12  = reinterpret_cast<const float2*>(bs1s);
    const float2* bs22  = reinterpret_cast<const float2*>(bs2s);

    // ---- one-time init ----
    #pragma unroll 4
    for (int it = 0; it < 16; it++) {           // Ws1/Ws2 -> fp8(16*w), 144B rows
        int q = it * NTH + tid;                 // float4 index 0..4095
        int n = q >> 5, k4 = (q & 31) * 4;
        float4 a = __ldg(reinterpret_cast<const float4*>(Ws1) + q);
        float4 b = __ldg(reinterpret_cast<const float4*>(Ws2) + q);
        uint32_t o = (uint32_t)(n * 144 + k4);
        sts32(sb + OFF_WS1 + o, pk4_e4m3(16.f * a.x, 16.f * a.y, 16.f * a.z, 16.f * a.w));
        sts32(sb + OFF_WS2 + o, pk4_e4m3(16.f * b.x, 16.f * b.y, 16.f * b.z, 16.f * b.w));
    }
    #pragma unroll 4
    for (int it = 0; it < 8; it++) {            // state <- fp8(x), 80B rows
        int q = it * NTH + tid;                 // word index 0..2047
        int r = q >> 4, c4 = (q & 15) << 2;
        float4 v = __ldg(reinterpret_cast<const float4*>(x) + (size_t)blockIdx.x * 2048 + q);
        sts32(stateT + (uint32_t)(r * 80 + c4), pk4_e4m3(v.x, v.y, v.z, v.w));
    }
    #pragma unroll
    for (int it = 0; it < 3; it++) {            // Wi buffer 0 (640 uint4)
        int q = it * NTH + tid;
        if (q < 640) {
            int o = q * 16;
            sts128(sb + OFF_WIB + o, *reinterpret_cast<const uint4*>(g_wi8[0] + o));
        }
    }
    if (tid < 128) {
        wicV[tid] = g_wic16[0][tid];
        wfsV[tid] = __ldg(wf + tid);
        bisV[tid] = 16.f * __ldg(bi + tid);
        bs1s[tid] = 16.f * __ldg(bs1 + tid);
        bs2s[tid] = __ldg(bs2 + tid);
    }
    __syncthreads();

    float acc[16][4];
    const float* zbase = z + (size_t)(tb + mrow0 + grp) * 64;

    #pragma unroll 1
    for (int i = 0; i < 64; i++) {
        const int cur = i & 1, nxt = cur ^ 1;
        const float bfv = __ldg(bf + i);
        float zr[4];
        #pragma unroll
        for (int kq = 0; kq < 4; kq++)
            zr[kq] = __ldg(zbase + kq * 512 + i);

        // ---- GEMM1: acc = state @ (Wi∘M)^T (K=64, A stride 80, B stride 80) ----
        gemm8<2, 80, 80>(stateT, sb + OFF_WIB + (uint32_t)cur * 10240u,
                         mrow0, ncol0, lane, acc);

        // ---- cooperative prefetch of step i+1 (sealed by boundary sync) ----
        if (i < 63) {
            const uint8_t* srcw = g_wi8[i + 1];
            const uint32_t dst = sb + OFF_WIB + (uint32_t)nxt * 10240u;
            #pragma unroll
            for (int it = 0; it < 3; it++) {
                int q = it * NTH + tid;
                if (q < 640) {
                    int o = q * 16;
                    sts128(dst + o, *reinterpret_cast<const uint4*>(srcw + o));
                }
            }
            if (tid < 128) {
                wicV[nxt * 128 + tid] = g_wic16[i + 1][tid];
                wfsV[nxt * 128 + tid] = __ldg(wf + (i + 1) * 128 + tid);
            } else {
                bisV[nxt * 128 + tid - 128] = 16.f * __ldg(bi + (i + 1) * 128 + tid - 128);
            }
        }

        // ---- epi1: h1_16 = relu(acc/8 + wic16*z + bi16) -> act1 (linear addrs) ----
        {
            const float2* wic2 = wic2a + cur * 64;
            const float2* bis2 = bis2a + cur * 64;
            #pragma unroll
            for (int mtl = 0; mtl < 2; mtl++) {
                int rA = mrow0 + 16 * mtl + grp;
                uint32_t adA = act1 + (uint32_t)(rA * 144 + ncol0 + 2 * qd);
                uint32_t adB = adA + 8u * 144u;
                float zA = zr[2 * mtl], zB = zr[2 * mtl + 1];
                #pragma unroll
                for (int nt = 0; nt < 8; nt++) {
                    int ci = (ncol0 >> 1) + 4 * nt + qd;
                    float2 wv = wic2[ci];
                    float2 bv = bis2[ci];
                    float* A = acc[mtl * 8 + nt];
                    float v0 = fmaxf(fmaf(A[0], 0.125f, fmaf(wv.x, zA, bv.x)), 0.f);
                    float v1 = fmaxf(fmaf(A[1], 0.125f, fmaf(wv.y, zA, bv.y)), 0.f);
                    float v2 = fmaxf(fmaf(A[2], 0.125f, fmaf(wv.x, zB, bv.x)), 0.f);
                    float v3 = fmaxf(fmaf(A[3], 0.125f, fmaf(wv.y, zB, bv.y)), 0.f);
                    sts_b16(adA + 8u * nt, pk2_e4m3(v0, v1));
                    sts_b16(adB + 8u * nt, pk2_e4m3(v2, v3));
                }
            }
        }
        PAIRBAR(pid);                           // pair's h1 rows complete

        // ---- GEMM2: acc = h1 @ Ws1^T (K=128, strides 144/144) ----
        gemm8<4, 144, 144>(act1, sb + OFF_WS1, mrow0, ncol0, lane, acc);

        // ---- epi2: h2_16 = relu(acc/16 + bs1_16) -> act2 (separate buffer) ----
        #pragma unroll
        for (int mtl = 0; mtl < 2; mtl++) {
            int rA = mrow0 + 16 * mtl + grp;
            uint32_t adA = act2 + (uint32_t)(rA * 144 + ncol0 + 2 * qd);
            uint32_t adB = adA + 8u * 144u;
            #pragma unroll
            for (int nt = 0; nt < 8; nt++) {
                int ci = (ncol0 >> 1) + 4 * nt + qd;
                float2 bv = bs12[ci];
                float* A = acc[mtl * 8 + nt];
                sts_b16(adA + 8u * nt,
                        pk2_e4m3(fmaxf(fmaf(A[0], 0.0625f, bv.x), 0.f),
                                 fmaxf(fmaf(A[1], 0.0625f, bv.y), 0.f)));
                sts_b16(adB + 8u * nt,
                        pk2_e4m3(fmaxf(fmaf(A[2], 0.0625f, bv.x), 0.f),
                                 fmaxf(fmaf(A[3], 0.0625f, bv.y), 0.f)));
            }
        }
        PAIRBAR(pid);                           // pair's h2 rows complete

        // ---- GEMM3: acc = h2 @ Ws2^T ----
        gemm8<4, 144, 144>(act2, sb + OFF_WS2, mrow0, ncol0, lane, acc);

        // ---- epi3: o = sigmoid( wf . relu(acc/256 + bs2) + bf ) ----
        {
            const float2* wfs2 = wfs2a + cur * 64;
            float pA0 = 0.f, pB0 = 0.f, pA1 = 0.f, pB1 = 0.f;
            #pragma unroll
            for (int nt = 0; nt < 8; nt++) {
                int ci = (ncol0 >> 1) + 4 * nt + qd;
                float2 wv = wfs2[ci];
                float2 bv = bs22[ci];
                float* A0 = acc[nt];
                float* A1 = acc[8 + nt];
                pA0 = fmaf(wv.x, fmaxf(fmaf(A0[0], 0.00390625f, bv.x), 0.f), pA0);
                pA0 = fmaf(wv.y, fmaxf(fmaf(A0[1], 0.00390625f, bv.y), 0.f), pA0);
                pB0 = fmaf(wv.x, fmaxf(fmaf(A0[2], 0.00390625f, bv.x), 0.f), pB0);
                pB0 = fmaf(wv.y, fmaxf(fmaf(A0[3], 0.00390625f, bv.y), 0.f), pB0);
                pA1 = fmaf(wv.x, fmaxf(fmaf(A1[0], 0.00390625f, bv.x), 0.f), pA1);
                pA1 = fmaf(wv.y, fmaxf(fmaf(A1[1], 0.00390625f, bv.y), 0.f), pA1);
                pB1 = fmaf(wv.x, fmaxf(fmaf(A1[2], 0.00390625f, bv.x), 0.f), pB1);
                pB1 = fmaf(wv.y, fmaxf(fmaf(A1[3], 0.00390625f, bv.y), 0.f), pB1);
            }
            pA0 += __shfl_xor_sync(0xffffffffu, pA0, 1);
            pA0 += __shfl_xor_sync(0xffffffffu, pA0, 2);
            pB0 += __shfl_xor_sync(0xffffffffu, pB0, 1);
            pB0 += __shfl_xor_sync(0xffffffffu, pB0, 2);
            pA1 += __shfl_xor_sync(0xffffffffu, pA1, 1);
            pA1 += __shfl_xor_sync(0xffffffffu, pA1, 2);
            pB1 += __shfl_xor_sync(0xffffffffu, pB1, 1);
            pB1 += __shfl_xor_sync(0xffffffffu, pB1, 2);
            if (qd == 0 && nhalf == 1) {        // publish col-half-1 partials
                partT[mrow0 + grp]      = pA0;
                partT[mrow0 + grp + 8]  = pB0;
                partT[mrow0 + grp + 16] = pA1;
                partT[mrow0 + grp + 24] = pB1;
            }
            PAIRBAR(pid);
            if (qd == 0 && nhalf == 0) {        // combine + sigmoid + store
                int r0 = mrow0 + grp;
                float t0 = pA0 + partT[r0]      + bfv;
                float t1 = pB0 + partT[r0 + 8]  + bfv;
                float t2 = pA1 + partT[r0 + 16] + bfv;
                float t3 = pB1 + partT[r0 + 24] + bfv;
                float o0 = 1.f / (1.f + __expf(-t0));
                float o1 = 1.f / (1.f + __expf(-t1));
                float o2 = 1.f / (1.f + __expf(-t2));
                float o3 = 1.f / (1.f + __expf(-t3));
                sts_b8(stateT + (uint32_t)((r0)      * 80 + i), (uint32_t)fp8b(o0));
                sts_b8(stateT + (uint32_t)((r0 + 8)  * 80 + i), (uint32_t)fp8b(o1));
                sts_b8(stateT + (uint32_t)((r0 + 16) * 80 + i), (uint32_t)fp8b(o2));
                sts_b8(stateT + (uint32_t)((r0 + 24) * 80 + i), (uint32_t)fp8b(o3));
                out[(size_t)(tb + r0)      * 64 + i] = o0;   // exact f32 output
                out[(size_t)(tb + r0 + 8)  * 64 + i] = o1;
                out[(size_t)(tb + r0 + 16) * 64 + i] = o2;
                out[(size_t)(tb + r0 + 24) * 64 + i] = o3;
            }
        }
        __syncthreads();                        // step boundary: state + bufs sealed
    }
}

extern "C" void kernel_launch(void* const* d_in, const int* in_sizes, int n_in,
                              void* d_out, int out_size) {
    const float* x   = (const float*)d_in[0];
    const float* z   = (const float*)d_in[1];
    const float* Mg  = (const float*)d_in[2];
    const float* Wi  = (const float*)d_in[3];
    const float* bi  = (const float*)d_in[4];
    const float* Ws1 = (const float*)d_in[5];
    const float* bs1 = (const float*)d_in[6];
    const float* Ws2 = (const float*)d_in[7];
    const float* bs2 = (const float*)d_in[8];
    const float* wf  = (const float*)d_in[9];
    const float* bf  = (const float*)d_in[10];
    float* out = (float*)d_out;

    const int B = in_sizes[0] / 64;              // 65536
    const int grid = B / TILE_M;                 // 512

    cudaFuncSetAttribute(gen_causal_kernel,
                         cudaFuncAttributeMaxDynamicSharedMemorySize, SMEM_TOTAL);
    prep_wi_kernel<<<64, 256>>>(Wi, Mg);
    gen_causal_kernel<<<grid, NTH, SMEM_TOTAL>>>(x, z, bi, Ws1, bs1,
                                                 Ws2, bs2, wf, bf, out);
}

// round 13
// speedup vs baseline: 1.1949x; 1.0329x over previous
// Generator_causal on GB300 (compute_103 baseline): warp-level FP8 e4m3 mma.sync +
// ldmatrix. CTA = 256 threads = ONE 128-row batch tile (8 warps = 4 warp pairs).
// R13: GEMM+epilogue FUSED per 16-col block (nj) so epilogue math interleaves
// with mma issue inside each warp (fills tensor-idle windows). A-fragments
// preloaded once per GEMM. Padded-stride linear layouts (no swizzle); adjacency
// mask folded into Wi offline; C-zero first-kstep mma; pair-local barriers;
// one CTA sync per step seals the Wi/vector prefetch. 2 CTAs/SM.
// Scales: state=fp8(v); WiM=fp8(128*Wi*M); Ws=fp8(16*Ws); h=fp8(16*h).
#include <cuda_runtime.h>
#include <cuda_bf16.h>
#include <cstdint>

#define NTH    256
#define TILE_M 128

// device scratch: pre-packed fp8(128*Wi*Mcol) tiles (80B row stride) + z-col wts
__device__ __align__(16) uint8_t g_wi8[64][10240];
__device__ float g_wic16[64][128];

// ---------------- SMEM map (bytes) ----------------
#define OFF_STATE  1024u      // 128 rows x 80B = 10240
#define OFF_ACT1   11264u     // h1: 128 x 144B = 18432
#define OFF_ACT2   29696u     // h2: 128 x 144B = 18432
#define OFF_WIB    48128u     // 2 bufs x (128 x 80B) = 20480
#define OFF_WS1    68608u     // 128 x 144B = 18432
#define OFF_WS2    87040u     // 18432
#define OFF_VEC    105472u    // wic[2][128]|wfs[2][128]|bis[2][128]|bs1|bs2|part
#define SMEM_TOTAL 110080u

// ---------------- helpers ----------------
__device__ __forceinline__ uint32_t smem_u32(const void* p) {
    uint32_t a;
    asm("{ .reg .u64 t; cvta.to.shared.u64 t, %1; cvt.u32.u64 %0, t; }" : "=r"(a) : "l"(p));
    return a;
}
__device__ __forceinline__ uint16_t pk2_e4m3(float lo, float hi) {
    uint16_t r;
    asm("cvt.rn.satfinite.e4m3x2.f32 %0, %1, %2;" : "=h"(r) : "f"(hi), "f"(lo));
    return r;
}
__device__ __forceinline__ uint32_t pk4_e4m3(float v0, float v1, float v2, float v3) {
    uint16_t lo = pk2_e4m3(v0, v1), hi = pk2_e4m3(v2, v3);
    uint32_t r;
    asm("mov.b32 %0, {%1, %2};" : "=r"(r) : "h"(lo), "h"(hi));
    return r;
}
__device__ __forceinline__ uint8_t fp8b(float v) { return (uint8_t)pk2_e4m3(v, 0.f); }
__device__ __forceinline__ void sts32(uint32_t addr, uint32_t v) {
    asm volatile("st.shared.b32 [%0], %1;" :: "r"(addr), "r"(v) : "memory");
}
__device__ __forceinline__ void sts_b16(uint32_t addr, uint16_t v) {
    asm volatile("st.shared.b16 [%0], %1;" :: "r"(addr), "h"(v) : "memory");
}
__device__ __forceinline__ void sts_b8(uint32_t addr, uint32_t v) {
    asm volatile("st.shared.u8 [%0], %1;" :: "r"(addr), "r"(v) : "memory");
}
__device__ __forceinline__ void sts128(uint32_t addr, uint4 v) {
    asm volatile("st.shared.v4.b32 [%0], {%1,%2,%3,%4};"
                 :: "r"(addr), "r"(v.x), "r"(v.y), "r"(v.z), "r"(v.w) : "memory");
}
__device__ __forceinline__ void ldsm4(uint32_t addr, uint32_t* r) {
    asm volatile("ldmatrix.sync.aligned.m8n8.x4.shared.b16 {%0,%1,%2,%3}, [%4];"
                 : "=r"(r[0]), "=r"(r[1]), "=r"(r[2]), "=r"(r[3]) : "r"(addr));
}
__device__ __forceinline__ void mma_fp8(float* c, const uint32_t* a, uint32_t b0, uint32_t b1) {
    asm volatile("mma.sync.aligned.m16n8k32.row.col.f32.e4m3.e4m3.f32 "
                 "{%0,%1,%2,%3}, {%4,%5,%6,%7}, {%8,%9}, {%0,%1,%2,%3};"
                 : "+f"(c[0]), "+f"(c[1]), "+f"(c[2]), "+f"(c[3])
                 : "r"(a[0]), "r"(a[1]), "r"(a[2]), "r"(a[3]), "r"(b0), "r"(b1));
}
__device__ __forceinline__ void mma_fp8_z(float* d, const uint32_t* a, uint32_t b0, uint32_t b1) {
    asm volatile("mma.sync.aligned.m16n8k32.row.col.f32.e4m3.e4m3.f32 "
                 "{%0,%1,%2,%3}, {%4,%5,%6,%7}, {%8,%9}, {%10,%11,%12,%13};"
                 : "=f"(d[0]), "=f"(d[1]), "=f"(d[2]), "=f"(d[3])
                 : "r"(a[0]), "r"(a[1]), "r"(a[2]), "r"(a[3]), "r"(b0), "r"(b1),
                   "f"(0.f), "f"(0.f), "f"(0.f), "f"(0.f));
}
#define PAIRBAR(id) asm volatile("bar.sync %0, 64;" :: "r"(id) : "memory")

// prologue: fold adjacency column into Wi -> fp8(128 * Wi * M[k][s]), 80B rows
__global__ void prep_wi_kernel(const float* __restrict__ Wi, const float* __restrict__ Mg) {
    const int s = blockIdx.x;
    const float* src = Wi + (size_t)s * 8320;
    for (int idx = threadIdx.x; idx < 8320; idx += 256) {
        int n = idx / 65, k = idx - n * 65;
        float v = __ldg(src + idx);
        if (k < 64) g_wi8[s][n * 80 + k] = fp8b(128.f * v * __ldg(Mg + k * 64 + s));
        else        g_wic16[s][n] = 16.f * v;
    }
}

__global__ void __launch_bounds__(NTH, 2)
gen_causal_kernel(const float* __restrict__ x,   const float* __restrict__ z,
                  const float* __restrict__ bi,  const float* __restrict__ Ws1,
                  const float* __restrict__ bs1, const float* __restrict__ Ws2,
                  const float* __restrict__ bs2, const float* __restrict__ wf,
                  const float* __restrict__ bf,  float* __restrict__ out)
{
    extern __shared__ char smem[];
    const int tid  = threadIdx.x;
    const int lane = tid & 31;
    const int w    = tid >> 5;
    const int pair = w >> 1;                    // 0..3
    const int mrow0 = pair << 5;                // pair's 32 rows
    const int nhalf = w & 1;
    const int ncol0 = nhalf << 6;               // warp's 64 cols
    const int pid   = 1 + pair;
    const int grp   = lane >> 2, qd = lane & 3;
    const int lr = lane & 7, lt = (lane >> 3) & 1, lh = lane >> 4;
    const int tb    = blockIdx.x * TILE_M;
    const uint32_t sb     = smem_u32(smem);
    const uint32_t stateT = sb + OFF_STATE;     // 80B rows
    const uint32_t act1   = sb + OFF_ACT1;      // 144B rows
    const uint32_t act2   = sb + OFF_ACT2;      // 144B rows
    const uint32_t ws1T   = sb + OFF_WS1;
    const uint32_t ws2T   = sb + OFF_WS2;

    float* wicV = reinterpret_cast<float*>(smem + OFF_VEC);   // [2][128]
    float* wfsV = wicV + 256;                                 // [2][128]
    float* bisV = wfsV + 256;                                 // [2][128] (16*bi)
    float* bs1s = bisV + 256;                                 // [128] (16*bs1)
    float* bs2s = bs1s + 128;                                 // [128]
    float* partT = bs2s + 128;                                // [128]
    const float2* wic2a = reinterpret_cast<const float2*>(wicV);
    const float2* wfs2a = reinterpret_cast<const float2*>(wfsV);
    const float2* bis2a = reinterpret_cast<const float2*>(bisV);
    const float2* bs12  = reinterpret_cast<const float2*>(bs1s);
    const float2* bs22  = reinterpret_cast<const float2*>(bs2s);

    // ---- one-time init ----
    #pragma unroll 4
    for (int it = 0; it < 16; it++) {           // Ws1/Ws2 -> fp8(16*w), 144B rows
        int q = it * NTH + tid;
        int n = q >> 5, k4 = (q & 31) * 4;
        float4 a = __ldg(reinterpret_cast<const float4*>(Ws1) + q);
        float4 b = __ldg(reinterpret_cast<const float4*>(Ws2) + q);
        uint32_t o = (uint32_t)(n * 144 + k4);
        sts32(ws1T + o, pk4_e4m3(16.f * a.x, 16.f * a.y, 16.f * a.z, 16.f * a.w));
        sts32(ws2T + o, pk4_e4m3(16.f * b.x, 16.f * b.y, 16.f * b.z, 16.f * b.w));
    }
    #pragma unroll 4
    for (int it = 0; it < 8; it++) {            // state <- fp8(x), 80B rows
        int q = it * NTH + tid;
        int r = q >> 4, c4 = (q & 15) << 2;
        float4 v = __ldg(reinterpret_cast<const float4*>(x) + (size_t)blockIdx.x * 2048 + q);
        sts32(stateT + (uint32_t)(r * 80 + c4), pk4_e4m3(v.x, v.y, v.z, v.w));
    }
    #pragma unroll
    for (int it = 0; it < 3; it++) {            // Wi buffer 0 (640 uint4)
        int q = it * NTH + tid;
        if (q < 640) {
            int o = q * 16;
            sts128(sb + OFF_WIB + o, *reinterpret_cast<const uint4*>(g_wi8[0] + o));
        }
    }
    if (tid < 128) {
        wicV[tid] = g_wic16[0][tid];
        wfsV[tid] = __ldg(wf + tid);
        bisV[tid] = 16.f * __ldg(bi + tid);
        bs1s[tid] = 16.f * __ldg(bs1 + tid);
        bs2s[tid] = __ldg(bs2 + tid);
    }
    __syncthreads();

    const float* zbase = z + (size_t)(tb + mrow0 + grp) * 64;

    #pragma unroll 1
    for (int i = 0; i < 64; i++) {
        const int cur = i & 1, nxt = cur ^ 1;
        const float bfv = __ldg(bf + i);
        float zr[4];
        #pragma unroll
        for (int kq = 0; kq < 4; kq++)
            zr[kq] = __ldg(zbase + kq * 512 + i);

        // ================= GEMM1 + epi1 fused (K=64, strides 80/80) ============
        {
            const uint32_t wib = sb + OFF_WIB + (uint32_t)cur * 10240u;
            uint32_t a1[2][2][4];                       // [ks][mt]
            #pragma unroll
            for (int mt = 0; mt < 2; mt++) {
                uint32_t ab = stateT + (uint32_t)((mrow0 + 16 * mt + lr + lt * 8) * 80)
                            + (uint32_t)(lh * 16);
                ldsm4(ab,       a1[0][mt]);
                ldsm4(ab + 32u, a1[1][mt]);
            }
            const float2* wic2 = wic2a + cur * 64;
            const float2* bis2 = bis2a + cur * 64;
            #pragma unroll
            for (int nj = 0; nj < 4; nj++) {
                float acc[2][2][4];                     // [mt][sub]
                uint32_t bb = wib + (uint32_t)((ncol0 + 16 * nj + lr + lh * 8) * 80)
                            + (uint32_t)(lt * 16);
                uint32_t b0[4], b1[4];
                ldsm4(bb,       b0);
                ldsm4(bb + 32u, b1);
                #pragma unroll
                for (int mt = 0; mt < 2; mt++) {
                    mma_fp8_z(acc[mt][0], a1[0][mt], b0[0], b0[1]);
                    mma_fp8_z(acc[mt][1], a1[0][mt], b0[2], b0[3]);
                    mma_fp8(acc[mt][0], a1[1][mt], b1[0], b1[1]);
                    mma_fp8(acc[mt][1], a1[1][mt], b1[2], b1[3]);
                }
                // epi1 for this 16-col block: h1_16 = relu(acc/8 + wic16*z + bi16)
                #pragma unroll
                for (int mt = 0; mt < 2; mt++) {
                    int rA = mrow0 + 16 * mt + grp;
                    float zA = zr[2 * mt], zB = zr[2 * mt + 1];
                    #pragma unroll
                    for (int sub = 0; sub < 2; sub++) {
                        int c = ncol0 + 16 * nj + 8 * sub + 2 * qd;
                        float2 wv = wic2[c >> 1];
                        float2 bv = bis2[c >> 1];
                        float* A = acc[mt][sub];
                        float v0 = fmaxf(fmaf(A[0], 0.125f, fmaf(wv.x, zA, bv.x)), 0.f);
                        float v1 = fmaxf(fmaf(A[1], 0.125f, fmaf(wv.y, zA, bv.y)), 0.f);
                        float v2 = fmaxf(fmaf(A[2], 0.125f, fmaf(wv.x, zB, bv.x)), 0.f);
                        float v3 = fmaxf(fmaf(A[3], 0.125f, fmaf(wv.y, zB, bv.y)), 0.f);
                        sts_b16(act1 + (uint32_t)(rA * 144 + c), pk2_e4m3(v0, v1));
                        sts_b16(act1 + (uint32_t)((rA + 8) * 144 + c), pk2_e4m3(v2, v3));
                    }
                }
            }
        }

        // ---- cooperative prefetch of step i+1 (sealed by boundary sync) ----
        if (i < 63) {
            const uint8_t* srcw = g_wi8[i + 1];
            const uint32_t dst = sb + OFF_WIB + (uint32_t)nxt * 10240u;
            #pragma unroll
            for (int it = 0; it < 3; it++) {
                int q = it * NTH + tid;
                if (q < 640) {
                    int o = q * 16;
                    sts128(dst + o, *reinterpret_cast<const uint4*>(srcw + o));
                }
            }
            if (tid < 128) {
                wicV[nxt * 128 + tid] = g_wic16[i + 1][tid];
                wfsV[nxt * 128 + tid] = __ldg(wf + (i + 1) * 128 + tid);
            } else {
                bisV[nxt * 128 + tid - 128] = 16.f * __ldg(bi + (i + 1) * 128 + tid - 128);
            }
        }
        PAIRBAR(pid);                           // pair's h1 rows complete

        // ================= GEMM2 + epi2 fused (K=128, strides 144/144) =========
        {
            uint32_t a2[4][2][4];                       // [ks][mt]
            #pragma unroll
            for (int mt = 0; mt < 2; mt++) {
                uint32_t ab = act1 + (uint32_t)((mrow0 + 16 * mt + lr + lt * 8) * 144)
                            + (uint32_t)(lh * 16);
                #pragma unroll
                for (int ks = 0; ks < 4; ks++)
                    ldsm4(ab + (uint32_t)(ks * 32), a2[ks][mt]);
            }
            #pragma unroll
            for (int nj = 0; nj < 4; nj++) {
                float acc[2][2][4];
                uint32_t bb = ws1T + (uint32_t)((ncol0 + 16 * nj + lr + lh * 8) * 144)
                            + (uint32_t)(lt * 16);
                #pragma unroll
                for (int ks = 0; ks < 4; ks++) {
                    uint32_t b[4];
                    ldsm4(bb + (uint32_t)(ks * 32), b);
                    #pragma unroll
                    for (int mt = 0; mt < 2; mt++) {
                        if (ks == 0) {
                            mma_fp8_z(acc[mt][0], a2[0][mt], b[0], b[1]);
                            mma_fp8_z(acc[mt][1], a2[0][mt], b[2], b[3]);
                        } else {
                            mma_fp8(acc[mt][0], a2[ks][mt], b[0], b[1]);
                            mma_fp8(acc[mt][1], a2[ks][mt], b[2], b[3]);
                        }
                    }
                }
                // epi2 for this block: h2_16 = relu(acc/16 + bs1_16) -> act2
                #pragma unroll
                for (int mt = 0; mt < 2; mt++) {
                    int rA = mrow0 + 16 * mt + grp;
                    #pragma unroll
                    for (int sub = 0; sub < 2; sub++) {
                        int c = ncol0 + 16 * nj + 8 * sub + 2 * qd;
                        float2 bv = bs12[c >> 1];
                        float* A = acc[mt][sub];
                        sts_b16(act2 + (uint32_t)(rA * 144 + c),
                                pk2_e4m3(fmaxf(fmaf(A[0], 0.0625f, bv.x), 0.f),
                                         fmaxf(fmaf(A[1], 0.0625f, bv.y), 0.f)));
                        sts_b16(act2 + (uint32_t)((rA + 8) * 144 + c),
                                pk2_e4m3(fmaxf(fmaf(A[2], 0.0625f, bv.x), 0.f),
                                         fmaxf(fmaf(A[3], 0.0625f, bv.y), 0.f)));
                    }
                }
            }
        }
        PAIRBAR(pid);                           // pair's h2 rows complete

        // ================= GEMM3 + epi3 fused ==================================
        {
            uint32_t a3[4][2][4];
            #pragma unroll
            for (int mt = 0; mt < 2; mt++) {
                uint32_t ab = act2 + (uint32_t)((mrow0 + 16 * mt + lr + lt * 8) * 144)
                            + (uint32_t)(lh * 16);
                #pragma unroll
                for (int ks = 0; ks < 4; ks++)
                    ldsm4(ab + (uint32_t)(ks * 32), a3[ks][mt]);
            }
            const float2* wfs2 = wfs2a + cur * 64;
            float pA0 = 0.f, pB0 = 0.f, pA1 = 0.f, pB1 = 0.f;
            #pragma unroll
            for (int nj = 0; nj < 4; nj++) {
                float acc[2][2][4];
                uint32_t bb = ws2T + (uint32_t)((ncol0 + 16 * nj + lr + lh * 8) * 144)
                            + (uint32_t)(lt * 16);
                #pragma unroll
                for (int ks = 0; ks < 4; ks++) {
                    uint32_t b[4];
                    ldsm4(bb + (uint32_t)(ks * 32), b);
                    #pragma unroll
                    for (int mt = 0; mt < 2; mt++) {
                        if (ks == 0) {
                            mma_fp8_z(acc[mt][0], a3[0][mt], b[0], b[1]);
                            mma_fp8_z(acc[mt][1], a3[0][mt], b[2], b[3]);
                        } else {
                            mma_fp8(acc[mt][0], a3[ks][mt], b[0], b[1]);
                            mma_fp8(acc[mt][1], a3[ks][mt], b[2], b[3]);
                        }
                    }
                }
                // epi3 partial dot for this block
                #pragma unroll
                for (int sub = 0; sub < 2; sub++) {
                    int c = ncol0 + 16 * nj + 8 * sub + 2 * qd;
                    float2 wv = wfs2[c >> 1];
                    float2 bv = bs22[c >> 1];
                    float* A0 = acc[0][sub];
                    float* A1 = acc[1][sub];
                    pA0 = fmaf(wv.x, fmaxf(fmaf(A0[0], 0.00390625f, bv.x), 0.f), pA0);
                    pA0 = fmaf(wv.y, fmaxf(fmaf(A0[1], 0.00390625f, bv.y), 0.f), pA0);
                    pB0 = fmaf(wv.x, fmaxf(fmaf(A0[2], 0.00390625f, bv.x), 0.f), pB0);
                    pB0 = fmaf(wv.y, fmaxf(fmaf(A0[3], 0.00390625f, bv.y), 0.f), pB0);
                    pA1 = fmaf(wv.x, fmaxf(fmaf(A1[0], 0.00390625f, bv.x), 0.f), pA1);
                    pA1 = fmaf(wv.y, fmaxf(fmaf(A1[1], 0.00390625f, bv.y), 0.f), pA1);
                    pB1 = fmaf(wv.x, fmaxf(fmaf(A1[2], 0.00390625f, bv.x), 0.f), pB1);
                    pB1 = fmaf(wv.y, fmaxf(fmaf(A1[3], 0.00390625f, bv.y), 0.f), pB1);
                }
            }
            pA0 += __shfl_xor_sync(0xffffffffu, pA0, 1);
            pA0 += __shfl_xor_sync(0xffffffffu, pA0, 2);
            pB0 += __shfl_xor_sync(0xffffffffu, pB0, 1);
            pB0 += __shfl_xor_sync(0xffffffffu, pB0, 2);
            pA1 += __shfl_xor_sync(0xffffffffu, pA1, 1);
            pA1 += __shfl_xor_sync(0xffffffffu, pA1, 2);
            pB1 += __shfl_xor_sync(0xffffffffu, pB1, 1);
            pB1 += __shfl_xor_sync(0xffffffffu, pB1, 2);
            if (qd == 0 && nhalf == 1) {        // publish col-half-1 partials
                partT[mrow0 + grp]      = pA0;
                partT[mrow0 + grp + 8]  = pB0;
                partT[mrow0 + grp + 16] = pA1;
                partT[mrow0 + grp + 24] = pB1;
            }
            PAIRBAR(pid);
            if (qd == 0 && nhalf == 0) {        // combine + sigmoid + store
                int r0 = mrow0 + grp;
                float t0 = pA0 + partT[r0]      + bfv;
                float t1 = pB0 + partT[r0 + 8]  + bfv;
                float t2 = pA1 + partT[r0 + 16] + bfv;
                float t3 = pB1 + partT[r0 + 24] + bfv;
                float o0 = 1.f / (1.f + __expf(-t0));
                float o1 = 1.f / (1.f + __expf(-t1));
                float o2 = 1.f / (1.f + __expf(-t2));
                float o3 = 1.f / (1.f + __expf(-t3));
                sts_b8(stateT + (uint32_t)((r0)      * 80 + i), (uint32_t)fp8b(o0));
                sts_b8(stateT + (uint32_t)((r0 + 8)  * 80 + i), (uint32_t)fp8b(o1));
                sts_b8(stateT + (uint32_t)((r0 + 16) * 80 + i), (uint32_t)fp8b(o2));
                sts_b8(stateT + (uint32_t)((r0 + 24) * 80 + i), (uint32_t)fp8b(o3));
                out[(size_t)(tb + r0)      * 64 + i] = o0;   // exact f32 output
                out[(size_t)(tb + r0 + 8)  * 64 + i] = o1;
                out[(size_t)(tb + r0 + 16) * 64 + i] = o2;
                out[(size_t)(tb + r0 + 24) * 64 + i] = o3;
            }
        }
        __syncthreads();                        // step boundary: state + bufs sealed
    }
}

extern "C" void kernel_launch(void* const* d_in, const int* in_sizes, int n_in,
                              void* d_out, int out_size) {
    const float* x   = (const float*)d_in[0];
    const float* z   = (const float*)d_in[1];
    const float* Mg  = (const float*)d_in[2];
    const float* Wi  = (const float*)d_in[3];
    const float* bi  = (const float*)d_in[4];
    const float* Ws1 = (const float*)d_in[5];
    const float* bs1 = (const float*)d_in[6];
    const float* Ws2 = (const float*)d_in[7];
    const float* bs2 = (const float*)d_in[8];
    const float* wf  = (const float*)d_in[9];
    const float* bf  = (const float*)d_in[10];
    float* out = (float*)d_out;

    const int B = in_sizes[0] / 64;              // 65536
    const int grid = B / TILE_M;                 // 512

    cudaFuncSetAttribute(gen_causal_kernel,
                         cudaFuncAttributeMaxDynamicSharedMemorySize, SMEM_TOTAL);
    prep_wi_kernel<<<64, 256>>>(Wi, Mg);
    gen_causal_kernel<<<grid, NTH, SMEM_TOTAL>>>(x, z, bi, Ws1, bs1,
                                                 Ws2, bs2, wf, bf, out);
}